// round 7
// baseline (speedup 1.0000x reference)
#include <cuda_runtime.h>
#include <math_constants.h>
#include <cstdint>

// Problem constants
#define N_ 4
#define T_ 2048
#define E_ 768
#define H_ 12
#define D_ 64
#define NT_ (N_*T_)    // 8192
#define NH_ (N_*H_)    // 48
#define EE_ (E_*E_)    // 589824

// Scratch. Q,K stored k-permuted (slot(k)=2*(k&3)+((k>>2)&1) per 8-group of d);
// V natural. x/W rounded+permuted along k.
__device__ float g_q[NH_*T_*D_];
__device__ float g_k[NH_*T_*D_];
__device__ float g_v[NH_*T_*D_];
__device__ float g_xr[NT_*E_];
__device__ float g_wr[3*EE_];

__device__ __forceinline__ uint32_t f2tf(float f) {
  uint32_t u;
  asm("cvt.rna.tf32.f32 %0, %1;" : "=r"(u) : "f"(f));
  return u;
}
__device__ __forceinline__ float ex2(float x) {
  float y;
  asm("ex2.approx.f32 %0, %1;" : "=f"(y) : "f"(x));
  return y;
}

// D = A*B + D, m16n8k8 tf32
__device__ __forceinline__ void mma8(float* c, uint32_t a0, uint32_t a1,
                                     uint32_t a2, uint32_t a3,
                                     uint32_t b0, uint32_t b1) {
  asm volatile(
      "mma.sync.aligned.m16n8k8.row.col.f32.tf32.tf32.f32 "
      "{%0,%1,%2,%3},{%4,%5,%6,%7},{%8,%9},{%0,%1,%2,%3};"
      : "+f"(c[0]), "+f"(c[1]), "+f"(c[2]), "+f"(c[3])
      : "r"(a0), "r"(a1), "r"(a2), "r"(a3), "r"(b0), "r"(b1));
}

__device__ __forceinline__ void cp16(uint32_t smem_addr, const void* gptr) {
  asm volatile("cp.async.cg.shared.global [%0], [%1], 16;"
               :: "r"(smem_addr), "l"(gptr));
}
__device__ __forceinline__ void cp_commit() {
  asm volatile("cp.async.commit_group;");
}
__device__ __forceinline__ void cp_wait0() {
  asm volatile("cp.async.wait_group 0;");
}

// ---------------------------------------------------------------------------
// Round x,Wq,Wk,Wv to tf32 and store k-PERMUTED into g_xr / g_wr.
// One launch; segment boundaries are multiples of blockDim -> uniform.
// ---------------------------------------------------------------------------
#define XQ4 (NT_*E_/4)   // 1572864
#define WQ4 (EE_/4)      // 147456
#define TOT4 (XQ4 + 3*WQ4)

__global__ __launch_bounds__(256) void round_kernel(
    const float* __restrict__ x, const float* __restrict__ wq,
    const float* __restrict__ wk, const float* __restrict__ wv) {
  int i = blockIdx.x * 256 + threadIdx.x;
  if (i >= TOT4) return;
  const float* src;
  float* dst;
  int li;
  if (i < XQ4)            { src = x;  dst = g_xr;           li = i; }
  else if (i < XQ4+WQ4)   { src = wq; dst = g_wr;           li = i - XQ4; }
  else if (i < XQ4+2*WQ4) { src = wk; dst = g_wr + EE_;     li = i - XQ4 - WQ4; }
  else                    { src = wv; dst = g_wr + 2*EE_;   li = i - XQ4 - 2*WQ4; }
  float4 v = reinterpret_cast<const float4*>(src)[li];
  int base = li * 4;
  int c = base % E_;            // col within row, multiple of 4
  int rowbase = base - c;
  int grp = c & ~7;
  int pq = (c >> 2) & 1;        // 0: k-offs 0..3 -> slots 0,2,4,6 ; 1: 4..7 -> 1,3,5,7
  float* d8 = dst + rowbase + grp + pq;
  d8[0] = __uint_as_float(f2tf(v.x));
  d8[2] = __uint_as_float(f2tf(v.y));
  d8[4] = __uint_as_float(f2tf(v.z));
  d8[6] = __uint_as_float(f2tf(v.w));
}

// ---------------------------------------------------------------------------
// QKV projection (tf32 mma): out[m][e] = sum_k x[m][k]*W[e][k]
// CTA 128x128, BK=32 double-buffered cp.async, 8 warps (wm4 x wn2), warp 32x64.
// Inputs k-permuted -> every fragment is one LDS.64. Stride 36 conflict-free.
// Epilogue: Q,K written d-permuted; V natural.
// ---------------------------------------------------------------------------
#define QST2 36

__global__ __launch_bounds__(256, 2) void qkv_kernel() {
  extern __shared__ uint32_t sm[];
  uint32_t* As = sm;                    // [2][128*36]
  uint32_t* Bs = sm + 2 * 128 * QST2;   // [2][128*36]

  const int which = blockIdx.z;
  const float* __restrict__ X = g_xr;
  const float* __restrict__ W = g_wr + which * EE_;
  float* __restrict__ out = (which == 0) ? g_q : ((which == 1) ? g_k : g_v);

  const int m0 = blockIdx.x * 128;
  const int e0 = blockIdx.y * 128;
  const int tid = threadIdx.x;
  const int lane = tid & 31;
  const int wid = tid >> 5;
  const int wm = wid & 3;
  const int wn = wid >> 2;
  const int g = lane >> 2;
  const int t4 = lane & 3;

  const int lr = tid >> 3;      // 0..31
  const int cq = tid & 7;       // float4 col 0..7

  const uint32_t as_b = (uint32_t)__cvta_generic_to_shared(As);
  const uint32_t bs_b = (uint32_t)__cvta_generic_to_shared(Bs);

#pragma unroll
  for (int p = 0; p < 4; p++) {
    int row = lr + p * 32;
    cp16(as_b + (row * QST2 + cq * 4) * 4, &X[(m0 + row) * E_ + cq * 4]);
    cp16(bs_b + (row * QST2 + cq * 4) * 4, &W[(e0 + row) * E_ + cq * 4]);
  }
  cp_commit();

  float acc[2][8][4] = {};

  for (int k0 = 0; k0 < E_; k0 += 32) {
    const int cur = (k0 >> 5) & 1;
    cp_wait0();
    __syncthreads();

    if (k0 + 32 < E_) {
      const int nxt = cur ^ 1;
#pragma unroll
      for (int p = 0; p < 4; p++) {
        int row = lr + p * 32;
        cp16(as_b + ((nxt * 128 + row) * QST2 + cq * 4) * 4,
             &X[(m0 + row) * E_ + k0 + 32 + cq * 4]);
        cp16(bs_b + ((nxt * 128 + row) * QST2 + cq * 4) * 4,
             &W[(e0 + row) * E_ + k0 + 32 + cq * 4]);
      }
      cp_commit();
    }

    const uint32_t* Ac = As + cur * 128 * QST2;
    const uint32_t* Bc = Bs + cur * 128 * QST2;

#pragma unroll
    for (int ks = 0; ks < 4; ks++) {
      const int koff = ks * 8 + 2 * t4;    // perm slot pair (k=t4, k=t4+4)
      uint2 alo[2], ahi[2];
#pragma unroll
      for (int i = 0; i < 2; i++) {
        int row = wm * 32 + i * 16 + g;
        alo[i] = *reinterpret_cast<const uint2*>(&Ac[row * QST2 + koff]);
        ahi[i] = *reinterpret_cast<const uint2*>(&Ac[(row + 8) * QST2 + koff]);
      }
#pragma unroll
      for (int j = 0; j < 8; j++) {
        int nrow = wn * 64 + j * 8 + g;
        uint2 b = *reinterpret_cast<const uint2*>(&Bc[nrow * QST2 + koff]);
#pragma unroll
        for (int i = 0; i < 2; i++)
          mma8(acc[i][j], alo[i].x, ahi[i].x, alo[i].y, ahi[i].y, b.x, b.y);
      }
    }
  }

  // Epilogue into [nh][t][d]. Q,K: d-permuted scalar stores; V: natural float2.
  const int h = (e0 >> 6) + wn;
#pragma unroll
  for (int i = 0; i < 2; i++) {
#pragma unroll
    for (int j = 0; j < 8; j++) {
      int d = j * 8 + 2 * t4;
      int m = m0 + wm * 32 + i * 16 + g;
#pragma unroll
      for (int half = 0; half < 2; half++) {
        int mm = m + half * 8;
        int n = mm >> 11, tt = mm & (T_ - 1);
        float v0 = __uint_as_float(f2tf(acc[i][j][2 * half]));
        float v1 = __uint_as_float(f2tf(acc[i][j][2 * half + 1]));
        float* base = &out[((size_t)(n * H_ + h) * T_ + tt) * D_];
        if (which == 2) {
          *reinterpret_cast<float2*>(base + d) = make_float2(v0, v1);
        } else {
          int grp = d & ~7;
          int p0 = 2 * (d & 3) + ((d >> 2) & 1);
          int p1 = 2 * ((d + 1) & 3) + (((d + 1) >> 2) & 1);
          base[grp + p0] = v0;
          base[grp + p1] = v1;
        }
      }
    }
  }
}

// ---------------------------------------------------------------------------
// Flash attention, tf32 mma, pipelined. Br=128, Bc=64, 4 warps, warp M=32.
// Q/K scratch k-permuted -> one LDS.64 per fragment pair (stride 68).
// V natural (stride 72, banks 8t4+g conflict-free).
// Softmax in log2 domain (scale folded). P C->A frags via quad shuffles.
// ---------------------------------------------------------------------------
#define AST 68
#define VST 72

__global__ __launch_bounds__(128, 2) void attn_kernel(float* __restrict__ out) {
  extern __shared__ uint32_t sm[];
  uint32_t* Qs = sm;                    // [128][68]
  uint32_t* Ks = Qs + 128 * AST;        // [2][64][68]
  uint32_t* Vs = Ks + 2 * 64 * AST;     // [2][64][72]

  const int qb = blockIdx.x;
  const int nh = blockIdx.y;
  const float* __restrict__ Qg = g_q + (size_t)nh * T_ * D_ + (size_t)qb * 128 * D_;
  const float* __restrict__ Kg = g_k + (size_t)nh * T_ * D_;
  const float* __restrict__ Vg = g_v + (size_t)nh * T_ * D_;

  const int tid = threadIdx.x;
  const int lane = tid & 31;
  const int wid = tid >> 5;           // 0..3
  const int g = lane >> 2;
  const int t4 = lane & 3;
  const int wbase = wid * 32;

  const int lr = tid >> 4;            // 0..7
  const int cq = tid & 15;            // 0..15

  const uint32_t qs_b = (uint32_t)__cvta_generic_to_shared(Qs);
  const uint32_t ks_b = (uint32_t)__cvta_generic_to_shared(Ks);
  const uint32_t vs_b = (uint32_t)__cvta_generic_to_shared(Vs);

#pragma unroll
  for (int p = 0; p < 16; p++) {
    int row = lr + p * 8;
    cp16(qs_b + (row * AST + cq * 4) * 4, &Qg[row * D_ + cq * 4]);
  }
#pragma unroll
  for (int p = 0; p < 8; p++) {
    int row = lr + p * 8;
    cp16(ks_b + (row * AST + cq * 4) * 4, &Kg[row * D_ + cq * 4]);
    cp16(vs_b + (row * VST + cq * 4) * 4, &Vg[row * D_ + cq * 4]);
  }
  cp_commit();

  float o[2][8][4] = {};
  float mi[4], li[4];
#pragma unroll
  for (int s = 0; s < 4; s++) { mi[s] = -CUDART_INF_F; li[s] = 0.f; }

  const int src_lo = (lane & 28) | (t4 >> 1);
  const int src_hi = src_lo + 2;
  const bool selhi = (t4 & 1);
  // scale * log2(e) folded: softmax in base-2 domain
  const float scl2 = 0.125f * 1.4426950408889634f;

  for (int kb = 0; kb < T_ / 64; kb++) {
    const int cur = kb & 1;
    cp_wait0();
    __syncthreads();

    if (kb + 1 < T_ / 64) {
      const int nxt = cur ^ 1;
      const size_t gbase = (size_t)(kb + 1) * 64;
#pragma unroll
      for (int p = 0; p < 8; p++) {
        int row = lr + p * 8;
        cp16(ks_b + ((nxt * 64 + row) * AST + cq * 4) * 4,
             &Kg[(gbase + row) * D_ + cq * 4]);
        cp16(vs_b + ((nxt * 64 + row) * VST + cq * 4) * 4,
             &Vg[(gbase + row) * D_ + cq * 4]);
      }
      cp_commit();
    }

    const uint32_t* Ksc = Ks + cur * 64 * AST;
    const uint32_t* Vsc = Vs + cur * 64 * VST;

    // ---- S = Q @ K^T : warp computes 32 x 64, LDS.64 fragments ----
    float sacc[2][8][4] = {};
#pragma unroll
    for (int ks = 0; ks < 8; ks++) {
      const int koff = ks * 8 + 2 * t4;
      uint2 alo[2], ahi[2];
#pragma unroll
      for (int i = 0; i < 2; i++) {
        int row = wbase + i * 16 + g;
        alo[i] = *reinterpret_cast<const uint2*>(&Qs[row * AST + koff]);
        ahi[i] = *reinterpret_cast<const uint2*>(&Qs[(row + 8) * AST + koff]);
      }
#pragma unroll
      for (int j = 0; j < 8; j++) {
        uint2 b = *reinterpret_cast<const uint2*>(&Ksc[(j * 8 + g) * AST + koff]);
#pragma unroll
        for (int i = 0; i < 2; i++)
          mma8(sacc[i][j], alo[i].x, ahi[i].x, alo[i].y, ahi[i].y, b.x, b.y);
      }
    }

    // ---- online softmax (log2 domain): 4 row-slots per thread ----
#pragma unroll
    for (int i = 0; i < 2; i++) {
#pragma unroll
      for (int rh = 0; rh < 2; rh++) {
        const int s = i * 2 + rh;
        float mx = -CUDART_INF_F;
#pragma unroll
        for (int j = 0; j < 8; j++) {
          sacc[i][j][2 * rh]     *= scl2;
          sacc[i][j][2 * rh + 1] *= scl2;
          mx = fmaxf(mx, fmaxf(sacc[i][j][2 * rh], sacc[i][j][2 * rh + 1]));
        }
        mx = fmaxf(mx, __shfl_xor_sync(0xffffffffu, mx, 1));
        mx = fmaxf(mx, __shfl_xor_sync(0xffffffffu, mx, 2));
        float mnew = fmaxf(mi[s], mx);
        float alpha = ex2(mi[s] - mnew);
        float rs = 0.f;
#pragma unroll
        for (int j = 0; j < 8; j++) {
          sacc[i][j][2 * rh]     = ex2(sacc[i][j][2 * rh] - mnew);
          sacc[i][j][2 * rh + 1] = ex2(sacc[i][j][2 * rh + 1] - mnew);
          rs += sacc[i][j][2 * rh] + sacc[i][j][2 * rh + 1];
        }
        rs += __shfl_xor_sync(0xffffffffu, rs, 1);
        rs += __shfl_xor_sync(0xffffffffu, rs, 2);
        li[s] = li[s] * alpha + rs;
        mi[s] = mnew;
#pragma unroll
        for (int j = 0; j < 8; j++) {
          o[i][j][2 * rh]     *= alpha;
          o[i][j][2 * rh + 1] *= alpha;
        }
      }
    }

    // ---- O += P @ V ; P A-fragments via quad shuffles ----
#pragma unroll
    for (int ks2 = 0; ks2 < 8; ks2++) {
      uint32_t pa[2][4];
#pragma unroll
      for (int i = 0; i < 2; i++) {
        float c0l = __shfl_sync(0xffffffffu, sacc[i][ks2][0], src_lo);
        float c1l = __shfl_sync(0xffffffffu, sacc[i][ks2][1], src_lo);
        float c0h = __shfl_sync(0xffffffffu, sacc[i][ks2][0], src_hi);
        float c1h = __shfl_sync(0xffffffffu, sacc[i][ks2][1], src_hi);
        float c2l = __shfl_sync(0xffffffffu, sacc[i][ks2][2], src_lo);
        float c3l = __shfl_sync(0xffffffffu, sacc[i][ks2][3], src_lo);
        float c2h = __shfl_sync(0xffffffffu, sacc[i][ks2][2], src_hi);
        float c3h = __shfl_sync(0xffffffffu, sacc[i][ks2][3], src_hi);
        pa[i][0] = f2tf(selhi ? c1l : c0l);
        pa[i][1] = f2tf(selhi ? c3l : c2l);
        pa[i][2] = f2tf(selhi ? c1h : c0h);
        pa[i][3] = f2tf(selhi ? c3h : c2h);
      }
#pragma unroll
      for (int j = 0; j < 8; j++) {
        uint32_t b0 = Vsc[(ks2 * 8 + t4) * VST + j * 8 + g];
        uint32_t b1 = Vsc[(ks2 * 8 + t4 + 4) * VST + j * 8 + g];
        mma8(o[0][j], pa[0][0], pa[0][1], pa[0][2], pa[0][3], b0, b1);
        mma8(o[1][j], pa[1][0], pa[1][1], pa[1][2], pa[1][3], b0, b1);
      }
    }
  }

  // ---- epilogue (natural layout) ----
  const int n = nh / H_;
  const int h = nh - n * H_;
#pragma unroll
  for (int i = 0; i < 2; i++) {
#pragma unroll
    for (int rh = 0; rh < 2; rh++) {
      float inv = 1.f / li[i * 2 + rh];
      int t = qb * 128 + wbase + i * 16 + rh * 8 + g;
#pragma unroll
      for (int j = 0; j < 8; j++) {
        int d = j * 8 + 2 * t4;
        *reinterpret_cast<float2*>(
            &out[((size_t)n * T_ + t) * E_ + h * D_ + d]) =
            make_float2(o[i][j][2 * rh] * inv, o[i][j][2 * rh + 1] * inv);
      }
    }
  }
}

extern "C" void kernel_launch(void* const* d_in, const int* in_sizes, int n_in,
                              void* d_out, int out_size) {
  const float* x  = (const float*)d_in[0];
  const float* Wq = (const float*)d_in[1];
  const float* Wk = (const float*)d_in[2];
  const float* Wv = (const float*)d_in[3];
  float* out = (float*)d_out;

  round_kernel<<<(TOT4 + 255) / 256, 256>>>(x, Wq, Wk, Wv);

  const int qkv_smem = 4 * 128 * QST2 * 4;  // 73728 B
  cudaFuncSetAttribute(qkv_kernel, cudaFuncAttributeMaxDynamicSharedMemorySize,
                       qkv_smem);
  dim3 gq(NT_ / 128, E_ / 128, 3);
  qkv_kernel<<<gq, 256, qkv_smem>>>();

  const int attn_smem = (128 * AST + 2 * 64 * AST + 2 * 64 * VST) * 4;  // 106496 B
  cudaFuncSetAttribute(attn_kernel, cudaFuncAttributeMaxDynamicSharedMemorySize,
                       attn_smem);
  dim3 ga(T_ / 128, NH_);
  attn_kernel<<<ga, 128, attn_smem>>>(out);
}

// round 8
// speedup vs baseline: 1.2309x; 1.2309x over previous
#include <cuda_runtime.h>
#include <math_constants.h>
#include <cstdint>

// Problem constants
#define N_ 4
#define T_ 2048
#define E_ 768
#define H_ 12
#define D_ 64
#define NT_ (N_*T_)    // 8192
#define NH_ (N_*H_)    // 48
#define EE_ (E_*E_)    // 589824

// Scratch (all natural layout, tf32-rounded values)
__device__ float g_q[NH_*T_*D_];
__device__ float g_k[NH_*T_*D_];
__device__ float g_v[NH_*T_*D_];
__device__ float g_xr[NT_*E_];
__device__ float g_wr[3*EE_];

__device__ __forceinline__ uint32_t f2tf(float f) {
  uint32_t u;
  asm("cvt.rna.tf32.f32 %0, %1;" : "=r"(u) : "f"(f));
  return u;
}
__device__ __forceinline__ float ex2(float x) {
  float y;
  asm("ex2.approx.f32 %0, %1;" : "=f"(y) : "f"(x));
  return y;
}

// D = A*B + D, m16n8k8 tf32
__device__ __forceinline__ void mma8(float* c, uint32_t a0, uint32_t a1,
                                     uint32_t a2, uint32_t a3,
                                     uint32_t b0, uint32_t b1) {
  asm volatile(
      "mma.sync.aligned.m16n8k8.row.col.f32.tf32.tf32.f32 "
      "{%0,%1,%2,%3},{%4,%5,%6,%7},{%8,%9},{%0,%1,%2,%3};"
      : "+f"(c[0]), "+f"(c[1]), "+f"(c[2]), "+f"(c[3])
      : "r"(a0), "r"(a1), "r"(a2), "r"(a3), "r"(b0), "r"(b1));
}

__device__ __forceinline__ void cp16(uint32_t smem_addr, const void* gptr) {
  asm volatile("cp.async.cg.shared.global [%0], [%1], 16;"
               :: "r"(smem_addr), "l"(gptr));
}
__device__ __forceinline__ void cp_commit() {
  asm volatile("cp.async.commit_group;");
}
__device__ __forceinline__ void cp_wait0() {
  asm volatile("cp.async.wait_group 0;");
}

// ---------------------------------------------------------------------------
// Round x,Wq,Wk,Wv to tf32 (natural layout), one merged launch.
// ---------------------------------------------------------------------------
#define XQ4 (NT_*E_/4)   // 1572864
#define WQ4 (EE_/4)      // 147456
#define TOT4 (XQ4 + 3*WQ4)

__global__ __launch_bounds__(256) void round_kernel(
    const float* __restrict__ x, const float* __restrict__ wq,
    const float* __restrict__ wk, const float* __restrict__ wv) {
  int i = blockIdx.x * 256 + threadIdx.x;
  if (i >= TOT4) return;
  const float* src;
  float* dst;
  int li;
  if (i < XQ4)            { src = x;  dst = g_xr;         li = i; }
  else if (i < XQ4+WQ4)   { src = wq; dst = g_wr;         li = i - XQ4; }
  else if (i < XQ4+2*WQ4) { src = wk; dst = g_wr + EE_;   li = i - XQ4 - WQ4; }
  else                    { src = wv; dst = g_wr + 2*EE_; li = i - XQ4 - 2*WQ4; }
  float4 v = reinterpret_cast<const float4*>(src)[li];
  v.x = __uint_as_float(f2tf(v.x));
  v.y = __uint_as_float(f2tf(v.y));
  v.z = __uint_as_float(f2tf(v.z));
  v.w = __uint_as_float(f2tf(v.w));
  reinterpret_cast<float4*>(dst)[li] = v;
}

// ---------------------------------------------------------------------------
// QKV projection (tf32 mma): out[m][e] = sum_k x[m][k]*W[e][k]
// CTA 128x128, BK=32 double-buffered cp.async, 8 warps (wm4 x wn2), warp 32x64.
// Plain row layout, stride 36 -> fragment LDS.32 banks 4g+t4 (conflict-free).
// ---------------------------------------------------------------------------
#define QST2 36

__global__ __launch_bounds__(256, 2) void qkv_kernel() {
  extern __shared__ uint32_t sm[];
  uint32_t* As = sm;                    // [2][128*36]
  uint32_t* Bs = sm + 2 * 128 * QST2;   // [2][128*36]

  const int which = blockIdx.z;
  const float* __restrict__ X = g_xr;
  const float* __restrict__ W = g_wr + which * EE_;
  float* __restrict__ out = (which == 0) ? g_q : ((which == 1) ? g_k : g_v);

  const int m0 = blockIdx.x * 128;
  const int e0 = blockIdx.y * 128;
  const int tid = threadIdx.x;
  const int lane = tid & 31;
  const int wid = tid >> 5;
  const int wm = wid & 3;
  const int wn = wid >> 2;
  const int g = lane >> 2;
  const int t4 = lane & 3;

  const int lr = tid >> 3;      // 0..31
  const int cq = tid & 7;       // float4 col 0..7

  const uint32_t as_b = (uint32_t)__cvta_generic_to_shared(As);
  const uint32_t bs_b = (uint32_t)__cvta_generic_to_shared(Bs);

#pragma unroll
  for (int p = 0; p < 4; p++) {
    int row = lr + p * 32;
    cp16(as_b + (row * QST2 + cq * 4) * 4, &X[(m0 + row) * E_ + cq * 4]);
    cp16(bs_b + (row * QST2 + cq * 4) * 4, &W[(e0 + row) * E_ + cq * 4]);
  }
  cp_commit();

  float acc[2][8][4] = {};

  for (int k0 = 0; k0 < E_; k0 += 32) {
    const int cur = (k0 >> 5) & 1;
    cp_wait0();
    __syncthreads();

    if (k0 + 32 < E_) {
      const int nxt = cur ^ 1;
#pragma unroll
      for (int p = 0; p < 4; p++) {
        int row = lr + p * 32;
        cp16(as_b + ((nxt * 128 + row) * QST2 + cq * 4) * 4,
             &X[(m0 + row) * E_ + k0 + 32 + cq * 4]);
        cp16(bs_b + ((nxt * 128 + row) * QST2 + cq * 4) * 4,
             &W[(e0 + row) * E_ + k0 + 32 + cq * 4]);
      }
      cp_commit();
    }

    const uint32_t* Ac = As + cur * 128 * QST2;
    const uint32_t* Bc = Bs + cur * 128 * QST2;

#pragma unroll
    for (int ks = 0; ks < 4; ks++) {
      const int koff = ks * 8 + t4;
      uint32_t a[2][4];
#pragma unroll
      for (int i = 0; i < 2; i++) {
        int row = wm * 32 + i * 16 + g;
        a[i][0] = Ac[row * QST2 + koff];
        a[i][1] = Ac[(row + 8) * QST2 + koff];
        a[i][2] = Ac[row * QST2 + koff + 4];
        a[i][3] = Ac[(row + 8) * QST2 + koff + 4];
      }
#pragma unroll
      for (int j = 0; j < 8; j++) {
        int nrow = wn * 64 + j * 8 + g;
        uint32_t b0 = Bc[nrow * QST2 + koff];
        uint32_t b1 = Bc[nrow * QST2 + koff + 4];
#pragma unroll
        for (int i = 0; i < 2; i++)
          mma8(acc[i][j], a[i][0], a[i][1], a[i][2], a[i][3], b0, b1);
      }
    }
  }

  // Epilogue into [nh][t][d] (natural), rounded to tf32 so attn skips cvt.
  const int h = (e0 >> 6) + wn;
#pragma unroll
  for (int i = 0; i < 2; i++) {
#pragma unroll
    for (int j = 0; j < 8; j++) {
      int d = j * 8 + 2 * t4;
      int m = m0 + wm * 32 + i * 16 + g;
      {
        int n = m >> 11, tt = m & (T_ - 1);
        *reinterpret_cast<float2*>(
            &out[((size_t)(n * H_ + h) * T_ + tt) * D_ + d]) =
            make_float2(__uint_as_float(f2tf(acc[i][j][0])),
                        __uint_as_float(f2tf(acc[i][j][1])));
      }
      {
        int m2 = m + 8;
        int n = m2 >> 11, tt = m2 & (T_ - 1);
        *reinterpret_cast<float2*>(
            &out[((size_t)(n * H_ + h) * T_ + tt) * D_ + d]) =
            make_float2(__uint_as_float(f2tf(acc[i][j][2])),
                        __uint_as_float(f2tf(acc[i][j][3])));
      }
    }
  }
}

// ---------------------------------------------------------------------------
// Flash attention, tf32 mma, pipelined. Br=128, Bc=64, 4 warps, warp M=32.
// K rows stored PERMUTED within 8-row groups (slot(r)=2*(r&3)+((r>>2)&1)):
// S columns come out in sigma-permuted kv order, which makes the S C-frag
// registers (c0,c2,c1,c3) exactly the PV A-fragment for natural V.
// -> zero shuffles between softmax and PV.
// Q/K stride 68 (banks 4g+t4 conflict-free); V stride 72 (banks 8t4+g).
// Softmax in log2 domain. K/V double-buffered via cp.async.
// ---------------------------------------------------------------------------
#define AST 68
#define VST 72

__global__ __launch_bounds__(128, 2) void attn_kernel(float* __restrict__ out) {
  extern __shared__ uint32_t sm[];
  uint32_t* Qs = sm;                    // [128][68]
  uint32_t* Ks = Qs + 128 * AST;        // [2][64][68]  (row-permuted)
  uint32_t* Vs = Ks + 2 * 64 * AST;     // [2][64][72]  (natural)

  const int qb = blockIdx.x;
  const int nh = blockIdx.y;
  const float* __restrict__ Qg = g_q + (size_t)nh * T_ * D_ + (size_t)qb * 128 * D_;
  const float* __restrict__ Kg = g_k + (size_t)nh * T_ * D_;
  const float* __restrict__ Vg = g_v + (size_t)nh * T_ * D_;

  const int tid = threadIdx.x;
  const int lane = tid & 31;
  const int wid = tid >> 5;           // 0..3
  const int g = lane >> 2;
  const int t4 = lane & 3;
  const int wbase = wid * 32;

  const int lr = tid >> 4;            // 0..7
  const int cq = tid & 15;            // 0..15
  // permuted destination row slot for K (within each 8-row group)
  const int plr = 2 * (lr & 3) + (lr >> 2);

  const uint32_t qs_b = (uint32_t)__cvta_generic_to_shared(Qs);
  const uint32_t ks_b = (uint32_t)__cvta_generic_to_shared(Ks);
  const uint32_t vs_b = (uint32_t)__cvta_generic_to_shared(Vs);

#pragma unroll
  for (int p = 0; p < 16; p++) {
    int row = lr + p * 8;
    cp16(qs_b + (row * AST + cq * 4) * 4, &Qg[row * D_ + cq * 4]);
  }
#pragma unroll
  for (int p = 0; p < 8; p++) {
    int row = lr + p * 8;
    int prow = plr + p * 8;
    cp16(ks_b + (prow * AST + cq * 4) * 4, &Kg[row * D_ + cq * 4]);
    cp16(vs_b + (row * VST + cq * 4) * 4, &Vg[row * D_ + cq * 4]);
  }
  cp_commit();

  float o[2][8][4] = {};
  float mi[4], li[4];
#pragma unroll
  for (int s = 0; s < 4; s++) { mi[s] = -CUDART_INF_F; li[s] = 0.f; }

  const float scl2 = 0.125f * 1.4426950408889634f;  // 1/sqrt(D) * log2(e)

  for (int kb = 0; kb < T_ / 64; kb++) {
    const int cur = kb & 1;
    cp_wait0();
    __syncthreads();

    if (kb + 1 < T_ / 64) {
      const int nxt = cur ^ 1;
      const size_t gbase = (size_t)(kb + 1) * 64;
#pragma unroll
      for (int p = 0; p < 8; p++) {
        int row = lr + p * 8;
        int prow = plr + p * 8;
        cp16(ks_b + ((nxt * 64 + prow) * AST + cq * 4) * 4,
             &Kg[(gbase + row) * D_ + cq * 4]);
        cp16(vs_b + ((nxt * 64 + row) * VST + cq * 4) * 4,
             &Vg[(gbase + row) * D_ + cq * 4]);
      }
      cp_commit();
    }

    const uint32_t* Ksc = Ks + cur * 64 * AST;
    const uint32_t* Vsc = Vs + cur * 64 * VST;

    // ---- S = Q @ K^T : warp computes 32 x 64 (columns sigma-permuted) ----
    float sacc[2][8][4] = {};
#pragma unroll
    for (int ks = 0; ks < 8; ks++) {
      const int koff = ks * 8 + t4;
      uint32_t a[2][4];
#pragma unroll
      for (int i = 0; i < 2; i++) {
        int row = wbase + i * 16 + g;
        a[i][0] = Qs[row * AST + koff];
        a[i][1] = Qs[(row + 8) * AST + koff];
        a[i][2] = Qs[row * AST + koff + 4];
        a[i][3] = Qs[(row + 8) * AST + koff + 4];
      }
#pragma unroll
      for (int j = 0; j < 8; j++) {
        uint32_t b0 = Ksc[(j * 8 + g) * AST + koff];
        uint32_t b1 = Ksc[(j * 8 + g) * AST + koff + 4];
#pragma unroll
        for (int i = 0; i < 2; i++)
          mma8(sacc[i][j], a[i][0], a[i][1], a[i][2], a[i][3], b0, b1);
      }
    }

    // ---- online softmax (log2 domain, column-order invariant) ----
#pragma unroll
    for (int i = 0; i < 2; i++) {
#pragma unroll
      for (int rh = 0; rh < 2; rh++) {
        const int s = i * 2 + rh;
        float mx = -CUDART_INF_F;
#pragma unroll
        for (int j = 0; j < 8; j++) {
          sacc[i][j][2 * rh]     *= scl2;
          sacc[i][j][2 * rh + 1] *= scl2;
          mx = fmaxf(mx, fmaxf(sacc[i][j][2 * rh], sacc[i][j][2 * rh + 1]));
        }
        mx = fmaxf(mx, __shfl_xor_sync(0xffffffffu, mx, 1));
        mx = fmaxf(mx, __shfl_xor_sync(0xffffffffu, mx, 2));
        float mnew = fmaxf(mi[s], mx);
        float alpha = ex2(mi[s] - mnew);
        float rs = 0.f;
#pragma unroll
        for (int j = 0; j < 8; j++) {
          sacc[i][j][2 * rh]     = ex2(sacc[i][j][2 * rh] - mnew);
          sacc[i][j][2 * rh + 1] = ex2(sacc[i][j][2 * rh + 1] - mnew);
          rs += sacc[i][j][2 * rh] + sacc[i][j][2 * rh + 1];
        }
        rs += __shfl_xor_sync(0xffffffffu, rs, 1);
        rs += __shfl_xor_sync(0xffffffffu, rs, 2);
        li[s] = li[s] * alpha + rs;
        mi[s] = mnew;
#pragma unroll
        for (int j = 0; j < 8; j++) {
          o[i][j][2 * rh]     *= alpha;
          o[i][j][2 * rh + 1] *= alpha;
        }
      }
    }

    // ---- O += P @ V : A-frag = (c0,c2,c1,c3) register relabel, no shuffles ----
#pragma unroll
    for (int ks2 = 0; ks2 < 8; ks2++) {
      uint32_t pa[2][4];
#pragma unroll
      for (int i = 0; i < 2; i++) {
        pa[i][0] = f2tf(sacc[i][ks2][0]);   // row g,   k = ks2*8 + t4
        pa[i][1] = f2tf(sacc[i][ks2][2]);   // row g+8, k = ks2*8 + t4
        pa[i][2] = f2tf(sacc[i][ks2][1]);   // row g,   k = ks2*8 + t4+4
        pa[i][3] = f2tf(sacc[i][ks2][3]);   // row g+8, k = ks2*8 + t4+4
      }
#pragma unroll
      for (int j = 0; j < 8; j++) {
        uint32_t b0 = Vsc[(ks2 * 8 + t4) * VST + j * 8 + g];
        uint32_t b1 = Vsc[(ks2 * 8 + t4 + 4) * VST + j * 8 + g];
        mma8(o[0][j], pa[0][0], pa[0][1], pa[0][2], pa[0][3], b0, b1);
        mma8(o[1][j], pa[1][0], pa[1][1], pa[1][2], pa[1][3], b0, b1);
      }
    }
  }

  // ---- epilogue (natural layout) ----
  const int n = nh / H_;
  const int h = nh - n * H_;
#pragma unroll
  for (int i = 0; i < 2; i++) {
#pragma unroll
    for (int rh = 0; rh < 2; rh++) {
      float inv = 1.f / li[i * 2 + rh];
      int t = qb * 128 + wbase + i * 16 + rh * 8 + g;
#pragma unroll
      for (int j = 0; j < 8; j++) {
        int d = j * 8 + 2 * t4;
        *reinterpret_cast<float2*>(
            &out[((size_t)n * T_ + t) * E_ + h * D_ + d]) =
            make_float2(o[i][j][2 * rh] * inv, o[i][j][2 * rh + 1] * inv);
      }
    }
  }
}

extern "C" void kernel_launch(void* const* d_in, const int* in_sizes, int n_in,
                              void* d_out, int out_size) {
  const float* x  = (const float*)d_in[0];
  const float* Wq = (const float*)d_in[1];
  const float* Wk = (const float*)d_in[2];
  const float* Wv = (const float*)d_in[3];
  float* out = (float*)d_out;

  round_kernel<<<(TOT4 + 255) / 256, 256>>>(x, Wq, Wk, Wv);

  const int qkv_smem = 4 * 128 * QST2 * 4;  // 73728 B
  cudaFuncSetAttribute(qkv_kernel, cudaFuncAttributeMaxDynamicSharedMemorySize,
                       qkv_smem);
  dim3 gq(NT_ / 128, E_ / 128, 3);
  qkv_kernel<<<gq, 256, qkv_smem>>>();

  const int attn_smem = (128 * AST + 2 * 64 * AST + 2 * 64 * VST) * 4;  // 106496 B
  cudaFuncSetAttribute(attn_kernel, cudaFuncAttributeMaxDynamicSharedMemorySize,
                       attn_smem);
  dim3 ga(T_ / 128, NH_);
  attn_kernel<<<ga, 128, attn_smem>>>(out);
}

// round 9
// speedup vs baseline: 2.1235x; 1.7252x over previous
#include <cuda_runtime.h>
#include <cuda_fp16.h>
#include <math_constants.h>
#include <cstdint>

// Problem constants
#define N_ 4
#define T_ 2048
#define E_ 768
#define H_ 12
#define D_ 64
#define NT_ (N_*T_)    // 8192
#define NH_ (N_*H_)    // 48
#define EE_ (E_*E_)    // 589824

// Scratch (fp16)
__device__ __half g_q[NH_*T_*D_];
__device__ __half g_k[NH_*T_*D_];
__device__ __half g_v[NH_*T_*D_];
__device__ __half g_xh[NT_*E_];
__device__ __half g_wh[3*EE_];

__device__ __forceinline__ float ex2(float x) {
  float y;
  asm("ex2.approx.f32 %0, %1;" : "=f"(y) : "f"(x));
  return y;
}
// pack (lo, hi) floats -> half2 in one reg
__device__ __forceinline__ uint32_t pack2(float lo, float hi) {
  uint32_t r;
  asm("cvt.rn.f16x2.f32 %0, %1, %2;" : "=r"(r) : "f"(hi), "f"(lo));
  return r;
}

// D = A*B + D, m16n8k16 f16 in, f32 accum
__device__ __forceinline__ void mmaf16(float* c, uint32_t a0, uint32_t a1,
                                       uint32_t a2, uint32_t a3,
                                       uint32_t b0, uint32_t b1) {
  asm volatile(
      "mma.sync.aligned.m16n8k16.row.col.f32.f16.f16.f32 "
      "{%0,%1,%2,%3},{%4,%5,%6,%7},{%8,%9},{%0,%1,%2,%3};"
      : "+f"(c[0]), "+f"(c[1]), "+f"(c[2]), "+f"(c[3])
      : "r"(a0), "r"(a1), "r"(a2), "r"(a3), "r"(b0), "r"(b1));
}

__device__ __forceinline__ void ldsm4(uint32_t& r0, uint32_t& r1, uint32_t& r2,
                                      uint32_t& r3, uint32_t addr) {
  asm volatile("ldmatrix.sync.aligned.m8n8.x4.shared.b16 {%0,%1,%2,%3}, [%4];"
               : "=r"(r0), "=r"(r1), "=r"(r2), "=r"(r3) : "r"(addr));
}
__device__ __forceinline__ void ldsm4t(uint32_t& r0, uint32_t& r1, uint32_t& r2,
                                       uint32_t& r3, uint32_t addr) {
  asm volatile("ldmatrix.sync.aligned.m8n8.x4.trans.shared.b16 {%0,%1,%2,%3}, [%4];"
               : "=r"(r0), "=r"(r1), "=r"(r2), "=r"(r3) : "r"(addr));
}

__device__ __forceinline__ void cp16(uint32_t smem_addr, const void* gptr) {
  asm volatile("cp.async.cg.shared.global [%0], [%1], 16;"
               :: "r"(smem_addr), "l"(gptr));
}
__device__ __forceinline__ void cp_commit() {
  asm volatile("cp.async.commit_group;");
}
__device__ __forceinline__ void cp_wait0() {
  asm volatile("cp.async.wait_group 0;");
}

// ---------------------------------------------------------------------------
// Convert x,Wq,Wk,Wv fp32 -> fp16, one merged launch.
// ---------------------------------------------------------------------------
#define XQ4 (NT_*E_/4)   // 1572864
#define WQ4 (EE_/4)      // 147456
#define TOT4 (XQ4 + 3*WQ4)

__global__ __launch_bounds__(256) void round_kernel(
    const float* __restrict__ x, const float* __restrict__ wq,
    const float* __restrict__ wk, const float* __restrict__ wv) {
  int i = blockIdx.x * 256 + threadIdx.x;
  if (i >= TOT4) return;
  const float* src;
  __half* dst;
  int li;
  if (i < XQ4)            { src = x;  dst = g_xh;         li = i; }
  else if (i < XQ4+WQ4)   { src = wq; dst = g_wh;         li = i - XQ4; }
  else if (i < XQ4+2*WQ4) { src = wk; dst = g_wh + EE_;   li = i - XQ4 - WQ4; }
  else                    { src = wv; dst = g_wh + 2*EE_; li = i - XQ4 - 2*WQ4; }
  float4 v = reinterpret_cast<const float4*>(src)[li];
  uint2 h;
  h.x = pack2(v.x, v.y);
  h.y = pack2(v.z, v.w);
  reinterpret_cast<uint2*>(dst)[li] = h;
}

// ---------------------------------------------------------------------------
// QKV projection (fp16 m16n8k16): out[m][e] = sum_k x[m][k]*W[e][k]
// CTA 128x128, BK=32 double-buffered cp.async, 8 warps (wm4 x wn2), warp 32x64.
// smem rows: 32 halfs + 8 pad = 40 halfs = 80B (ldsm conflict-free: 20g mod 32).
// ---------------------------------------------------------------------------
#define QSTH 40   // halfs
#define QROW 80   // bytes
#define QBUF (128*QROW)

__global__ __launch_bounds__(256, 2) void qkv_kernel() {
  extern __shared__ __half smh[];
  const uint32_t sbase = (uint32_t)__cvta_generic_to_shared(smh);
  const uint32_t as_b = sbase;                 // [2][128][40h]
  const uint32_t bs_b = sbase + 2 * QBUF;      // [2][128][40h]

  const int which = blockIdx.z;
  const __half* __restrict__ X = g_xh;
  const __half* __restrict__ W = g_wh + which * EE_;
  __half* __restrict__ out = (which == 0) ? g_q : ((which == 1) ? g_k : g_v);

  const int m0 = blockIdx.x * 128;
  const int e0 = blockIdx.y * 128;
  const int tid = threadIdx.x;
  const int lane = tid & 31;
  const int wid = tid >> 5;
  const int wm = wid & 3;
  const int wn = wid >> 2;
  const int g = lane >> 2;
  const int t4 = lane & 3;

  // loader: row = tid>>2 (0..63, x2 passes), 16B chunk = tid&3
  const int lrow = tid >> 2;
  const int c4 = tid & 3;

  // ldsm lane address components
  const int l15 = lane & 15;
  const int kh = (lane >> 4) * 16;             // byte offset of k-half (8 halfs)
  const int e8 = ((lane >> 3) & 1) * 8;
  const int l7 = lane & 7;

  // prologue: buffer 0
#pragma unroll
  for (int p = 0; p < 2; p++) {
    int row = lrow + p * 64;
    cp16(as_b + row * QROW + c4 * 16, &X[(m0 + row) * E_ + c4 * 8]);
    cp16(bs_b + row * QROW + c4 * 16, &W[(e0 + row) * E_ + c4 * 8]);
  }
  cp_commit();

  float acc[2][8][4] = {};

  for (int k0 = 0; k0 < E_; k0 += 32) {
    const int cur = (k0 >> 5) & 1;
    cp_wait0();
    __syncthreads();

    if (k0 + 32 < E_) {
      const int nxt = cur ^ 1;
#pragma unroll
      for (int p = 0; p < 2; p++) {
        int row = lrow + p * 64;
        cp16(as_b + nxt * QBUF + row * QROW + c4 * 16,
             &X[(m0 + row) * E_ + k0 + 32 + c4 * 8]);
        cp16(bs_b + nxt * QBUF + row * QROW + c4 * 16,
             &W[(e0 + row) * E_ + k0 + 32 + c4 * 8]);
      }
      cp_commit();
    }

    const uint32_t ab = as_b + cur * QBUF;
    const uint32_t bb = bs_b + cur * QBUF;

#pragma unroll
    for (int ks = 0; ks < 2; ks++) {
      uint32_t a[2][4];
#pragma unroll
      for (int i = 0; i < 2; i++)
        ldsm4(a[i][0], a[i][1], a[i][2], a[i][3],
              ab + (wm * 32 + i * 16 + l15) * QROW + ks * 32 + kh);
#pragma unroll
      for (int jp = 0; jp < 4; jp++) {
        uint32_t b0, b1, b2, b3;
        ldsm4(b0, b1, b2, b3,
              bb + (wn * 64 + jp * 16 + e8 + l7) * QROW + ks * 32 + kh);
#pragma unroll
        for (int i = 0; i < 2; i++) {
          mmaf16(acc[i][2 * jp],     a[i][0], a[i][1], a[i][2], a[i][3], b0, b2);
          mmaf16(acc[i][2 * jp + 1], a[i][0], a[i][1], a[i][2], a[i][3], b1, b3);
        }
      }
    }
  }

  // Epilogue: half2 stores into [nh][t][d] (fp16)
  const int h = (e0 >> 6) + wn;
#pragma unroll
  for (int i = 0; i < 2; i++) {
#pragma unroll
    for (int j = 0; j < 8; j++) {
      int d = j * 8 + 2 * t4;
      int m = m0 + wm * 32 + i * 16 + g;
#pragma unroll
      for (int half = 0; half < 2; half++) {
        int mm = m + half * 8;
        int n = mm >> 11, tt = mm & (T_ - 1);
        uint32_t hv = pack2(acc[i][j][2 * half], acc[i][j][2 * half + 1]);
        *reinterpret_cast<uint32_t*>(
            &out[((size_t)(n * H_ + h) * T_ + tt) * D_ + d]) = hv;
      }
    }
  }
}

// ---------------------------------------------------------------------------
// Flash attention fp16 m16n8k16. Br=128, Bc=64, 4 warps, warp M=32.
// All tiles natural layout, row stride 72 halfs = 144B (ldsm conflict-free).
// Q/K A/B frags via ldsm.x4; V B-frags via ldsm.x4.trans (HW transpose).
// P C-frags pack natively into PV A-frags (half2) -> no shuffles/permutes.
// K/V double-buffered cp.async; softmax in log2 domain.
// ---------------------------------------------------------------------------
#define ASTH 72      // halfs
#define AROW 144     // bytes
#define KVBUF (64*AROW)

__global__ __launch_bounds__(128, 2) void attn_kernel(float* __restrict__ out) {
  extern __shared__ __half smh[];
  const uint32_t sbase = (uint32_t)__cvta_generic_to_shared(smh);
  const uint32_t qs_b = sbase;                       // [128][72h]
  const uint32_t ks_b = sbase + 128 * AROW;          // [2][64][72h]
  const uint32_t vs_b = ks_b + 2 * KVBUF;            // [2][64][72h]

  const int qb = blockIdx.x;
  const int nh = blockIdx.y;
  const __half* __restrict__ Qg = g_q + (size_t)nh * T_ * D_ + (size_t)qb * 128 * D_;
  const __half* __restrict__ Kg = g_k + (size_t)nh * T_ * D_;
  const __half* __restrict__ Vg = g_v + (size_t)nh * T_ * D_;

  const int tid = threadIdx.x;
  const int lane = tid & 31;
  const int wid = tid >> 5;           // 0..3
  const int g = lane >> 2;
  const int t4 = lane & 3;
  const int wbase = wid * 32;

  // loader: row = tid>>3 (0..15), 16B chunk = tid&7
  const int lrow = tid >> 3;
  const int c8 = tid & 7;

  // ldsm lane components
  const int l15 = lane & 15;
  const int kh = (lane >> 4) * 16;    // byte offset: which k/d 8-half group
  const int e8 = ((lane >> 3) & 1) * 8;
  const int l7 = lane & 7;

  // prologue: Q (128 rows) + K/V tile 0
#pragma unroll
  for (int p = 0; p < 8; p++) {
    int row = lrow + p * 16;
    cp16(qs_b + row * AROW + c8 * 16, &Qg[row * D_ + c8 * 8]);
  }
#pragma unroll
  for (int p = 0; p < 4; p++) {
    int row = lrow + p * 16;
    cp16(ks_b + row * AROW + c8 * 16, &Kg[row * D_ + c8 * 8]);
    cp16(vs_b + row * AROW + c8 * 16, &Vg[row * D_ + c8 * 8]);
  }
  cp_commit();

  float o[2][8][4] = {};
  float mi[4], li[4];
#pragma unroll
  for (int s = 0; s < 4; s++) { mi[s] = -CUDART_INF_F; li[s] = 0.f; }

  const float scl2 = 0.125f * 1.4426950408889634f;  // 1/sqrt(D) * log2(e)

  for (int kb = 0; kb < T_ / 64; kb++) {
    const int cur = kb & 1;
    cp_wait0();
    __syncthreads();

    if (kb + 1 < T_ / 64) {
      const int nxt = cur ^ 1;
      const size_t gbase = (size_t)(kb + 1) * 64;
#pragma unroll
      for (int p = 0; p < 4; p++) {
        int row = lrow + p * 16;
        cp16(ks_b + nxt * KVBUF + row * AROW + c8 * 16,
             &Kg[(gbase + row) * D_ + c8 * 8]);
        cp16(vs_b + nxt * KVBUF + row * AROW + c8 * 16,
             &Vg[(gbase + row) * D_ + c8 * 8]);
      }
      cp_commit();
    }

    const uint32_t kbuf = ks_b + cur * KVBUF;
    const uint32_t vbuf = vs_b + cur * KVBUF;

    // ---- S = Q @ K^T : warp 32 x 64, k-steps of 16 ----
    float sacc[2][8][4] = {};
#pragma unroll
    for (int ks = 0; ks < 4; ks++) {
      uint32_t a[2][4];
#pragma unroll
      for (int i = 0; i < 2; i++)
        ldsm4(a[i][0], a[i][1], a[i][2], a[i][3],
              qs_b + (wbase + i * 16 + l15) * AROW + ks * 32 + kh);
#pragma unroll
      for (int jp = 0; jp < 4; jp++) {
        uint32_t b0, b1, b2, b3;
        ldsm4(b0, b1, b2, b3,
              kbuf + (jp * 16 + e8 + l7) * AROW + ks * 32 + kh);
#pragma unroll
        for (int i = 0; i < 2; i++) {
          mmaf16(sacc[i][2 * jp],     a[i][0], a[i][1], a[i][2], a[i][3], b0, b2);
          mmaf16(sacc[i][2 * jp + 1], a[i][0], a[i][1], a[i][2], a[i][3], b1, b3);
        }
      }
    }

    // ---- online softmax (log2 domain): 4 row-slots per thread ----
#pragma unroll
    for (int i = 0; i < 2; i++) {
#pragma unroll
      for (int rh = 0; rh < 2; rh++) {
        const int s = i * 2 + rh;
        float mx = -CUDART_INF_F;
#pragma unroll
        for (int j = 0; j < 8; j++) {
          sacc[i][j][2 * rh]     *= scl2;
          sacc[i][j][2 * rh + 1] *= scl2;
          mx = fmaxf(mx, fmaxf(sacc[i][j][2 * rh], sacc[i][j][2 * rh + 1]));
        }
        mx = fmaxf(mx, __shfl_xor_sync(0xffffffffu, mx, 1));
        mx = fmaxf(mx, __shfl_xor_sync(0xffffffffu, mx, 2));
        float mnew = fmaxf(mi[s], mx);
        float alpha = ex2(mi[s] - mnew);
        float rs = 0.f;
#pragma unroll
        for (int j = 0; j < 8; j++) {
          sacc[i][j][2 * rh]     = ex2(sacc[i][j][2 * rh] - mnew);
          sacc[i][j][2 * rh + 1] = ex2(sacc[i][j][2 * rh + 1] - mnew);
          rs += sacc[i][j][2 * rh] + sacc[i][j][2 * rh + 1];
        }
        rs += __shfl_xor_sync(0xffffffffu, rs, 1);
        rs += __shfl_xor_sync(0xffffffffu, rs, 2);
        li[s] = li[s] * alpha + rs;
        mi[s] = mnew;
#pragma unroll
        for (int j = 0; j < 8; j++) {
          o[i][j][2 * rh]     *= alpha;
          o[i][j][2 * rh + 1] *= alpha;
        }
      }
    }

    // ---- O += P @ V : A-frags packed from C-frags, B via ldsm.trans ----
#pragma unroll
    for (int ks2 = 0; ks2 < 4; ks2++) {
      uint32_t pa[2][4];
#pragma unroll
      for (int i = 0; i < 2; i++) {
        pa[i][0] = pack2(sacc[i][2 * ks2][0],     sacc[i][2 * ks2][1]);
        pa[i][1] = pack2(sacc[i][2 * ks2][2],     sacc[i][2 * ks2][3]);
        pa[i][2] = pack2(sacc[i][2 * ks2 + 1][0], sacc[i][2 * ks2 + 1][1]);
        pa[i][3] = pack2(sacc[i][2 * ks2 + 1][2], sacc[i][2 * ks2 + 1][3]);
      }
#pragma unroll
      for (int jp = 0; jp < 4; jp++) {
        uint32_t v0, v1, v2, v3;
        // rows s = ks2*16 + e8 + l7 ; cols d = jp*16 + (lane>>4)*8
        ldsm4t(v0, v1, v2, v3,
               vbuf + (ks2 * 16 + e8 + l7) * AROW + jp * 32 + kh);
#pragma unroll
        for (int i = 0; i < 2; i++) {
          mmaf16(o[i][2 * jp],     pa[i][0], pa[i][1], pa[i][2], pa[i][3], v0, v1);
          mmaf16(o[i][2 * jp + 1], pa[i][0], pa[i][1], pa[i][2], pa[i][3], v2, v3);
        }
      }
    }
  }

  // ---- epilogue (fp32 output, natural layout) ----
  const int n = nh / H_;
  const int h = nh - n * H_;
#pragma unroll
  for (int i = 0; i < 2; i++) {
#pragma unroll
    for (int rh = 0; rh < 2; rh++) {
      float inv = 1.f / li[i * 2 + rh];
      int t = qb * 128 + wbase + i * 16 + rh * 8 + g;
#pragma unroll
      for (int j = 0; j < 8; j++) {
        int d = j * 8 + 2 * t4;
        *reinterpret_cast<float2*>(
            &out[((size_t)n * T_ + t) * E_ + h * D_ + d]) =
            make_float2(o[i][j][2 * rh] * inv, o[i][j][2 * rh + 1] * inv);
      }
    }
  }
}

extern "C" void kernel_launch(void* const* d_in, const int* in_sizes, int n_in,
                              void* d_out, int out_size) {
  const float* x  = (const float*)d_in[0];
  const float* Wq = (const float*)d_in[1];
  const float* Wk = (const float*)d_in[2];
  const float* Wv = (const float*)d_in[3];
  float* out = (float*)d_out;

  round_kernel<<<(TOT4 + 255) / 256, 256>>>(x, Wq, Wk, Wv);

  const int qkv_smem = 4 * QBUF;   // 40960 B
  cudaFuncSetAttribute(qkv_kernel, cudaFuncAttributeMaxDynamicSharedMemorySize,
                       qkv_smem);
  dim3 gq(NT_ / 128, E_ / 128, 3);
  qkv_kernel<<<gq, 256, qkv_smem>>>();

  const int attn_smem = 128 * AROW + 4 * KVBUF;  // 55296 B
  cudaFuncSetAttribute(attn_kernel, cudaFuncAttributeMaxDynamicSharedMemorySize,
                       attn_smem);
  dim3 ga(T_ / 128, NH_);
  attn_kernel<<<ga, 128, attn_smem>>>(out);
}

// round 11
// speedup vs baseline: 2.1586x; 1.0165x over previous
#include <cuda_runtime.h>
#include <cuda_fp16.h>
#include <math_constants.h>
#include <cstdint>

// Problem constants
#define N_ 4
#define T_ 2048
#define E_ 768
#define H_ 12
#define D_ 64
#define NT_ (N_*T_)    // 8192
#define NH_ (N_*H_)    // 48
#define EE_ (E_*E_)    // 589824

// Scratch (fp16). Q is pre-scaled by 1/sqrt(D)*log2(e).
__device__ __half g_q[NH_*T_*D_];
__device__ __half g_k[NH_*T_*D_];
__device__ __half g_v[NH_*T_*D_];
__device__ __half g_xh[NT_*E_];
__device__ __half g_wh[3*EE_];

__device__ __forceinline__ float ex2(float x) {
  float y;
  asm("ex2.approx.f32 %0, %1;" : "=f"(y) : "f"(x));
  return y;
}
__device__ __forceinline__ uint32_t pack2(float lo, float hi) {
  uint32_t r;
  asm("cvt.rn.f16x2.f32 %0, %1, %2;" : "=r"(r) : "f"(hi), "f"(lo));
  return r;
}

// D = A*B + D, m16n8k16 f16 in, f32 accum
__device__ __forceinline__ void mmaf16(float* c, uint32_t a0, uint32_t a1,
                                       uint32_t a2, uint32_t a3,
                                       uint32_t b0, uint32_t b1) {
  asm volatile(
      "mma.sync.aligned.m16n8k16.row.col.f32.f16.f16.f32 "
      "{%0,%1,%2,%3},{%4,%5,%6,%7},{%8,%9},{%0,%1,%2,%3};"
      : "+f"(c[0]), "+f"(c[1]), "+f"(c[2]), "+f"(c[3])
      : "r"(a0), "r"(a1), "r"(a2), "r"(a3), "r"(b0), "r"(b1));
}

__device__ __forceinline__ void ldsm4(uint32_t& r0, uint32_t& r1, uint32_t& r2,
                                      uint32_t& r3, uint32_t addr) {
  asm volatile("ldmatrix.sync.aligned.m8n8.x4.shared.b16 {%0,%1,%2,%3}, [%4];"
               : "=r"(r0), "=r"(r1), "=r"(r2), "=r"(r3) : "r"(addr));
}
__device__ __forceinline__ void ldsm4t(uint32_t& r0, uint32_t& r1, uint32_t& r2,
                                       uint32_t& r3, uint32_t addr) {
  asm volatile("ldmatrix.sync.aligned.m8n8.x4.trans.shared.b16 {%0,%1,%2,%3}, [%4];"
               : "=r"(r0), "=r"(r1), "=r"(r2), "=r"(r3) : "r"(addr));
}

__device__ __forceinline__ void cp16(uint32_t smem_addr, const void* gptr) {
  asm volatile("cp.async.cg.shared.global [%0], [%1], 16;"
               :: "r"(smem_addr), "l"(gptr));
}
__device__ __forceinline__ void cp_commit() {
  asm volatile("cp.async.commit_group;");
}
__device__ __forceinline__ void cp_wait0() {
  asm volatile("cp.async.wait_group 0;");
}

// ---------------------------------------------------------------------------
// Convert x,Wq,Wk,Wv fp32 -> fp16, one merged launch.
// ---------------------------------------------------------------------------
#define XQ4 (NT_*E_/4)   // 1572864
#define WQ4 (EE_/4)      // 147456
#define TOT4 (XQ4 + 3*WQ4)

__global__ __launch_bounds__(256) void round_kernel(
    const float* __restrict__ x, const float* __restrict__ wq,
    const float* __restrict__ wk, const float* __restrict__ wv) {
  int i = blockIdx.x * 256 + threadIdx.x;
  if (i >= TOT4) return;
  const float* src;
  __half* dst;
  int li;
  if (i < XQ4)            { src = x;  dst = g_xh;         li = i; }
  else if (i < XQ4+WQ4)   { src = wq; dst = g_wh;         li = i - XQ4; }
  else if (i < XQ4+2*WQ4) { src = wk; dst = g_wh + EE_;   li = i - XQ4 - WQ4; }
  else                    { src = wv; dst = g_wh + 2*EE_; li = i - XQ4 - 2*WQ4; }
  float4 v = reinterpret_cast<const float4*>(src)[li];
  uint2 h;
  h.x = pack2(v.x, v.y);
  h.y = pack2(v.z, v.w);
  reinterpret_cast<uint2*>(dst)[li] = h;
}

// ---------------------------------------------------------------------------
// QKV projection (fp16 m16n8k16): out[m][e] = sum_k x[m][k]*W[e][k]
// CTA 128x128, BK=32 double-buffered cp.async, 8 warps (wm4 x wn2), warp 32x64.
// smem rows: 32 halfs + 8 pad = 40 halfs = 80B (ldsm conflict-free).
// Q output pre-scaled by 1/sqrt(D)*log2(e) so attn softmax needs no scaling.
// ---------------------------------------------------------------------------
#define QSTH 40   // halfs
#define QROW 80   // bytes
#define QBUF (128*QROW)

__global__ __launch_bounds__(256, 2) void qkv_kernel() {
  extern __shared__ __half smh[];
  const uint32_t sbase = (uint32_t)__cvta_generic_to_shared(smh);
  const uint32_t as_b = sbase;                 // [2][128][40h]
  const uint32_t bs_b = sbase + 2 * QBUF;      // [2][128][40h]

  const int which = blockIdx.z;
  const __half* __restrict__ X = g_xh;
  const __half* __restrict__ W = g_wh + which * EE_;
  __half* __restrict__ out = (which == 0) ? g_q : ((which == 1) ? g_k : g_v);
  const float osc = (which == 0) ? 0.18033688011111793f : 1.0f;  // 0.125*log2e

  const int m0 = blockIdx.x * 128;
  const int e0 = blockIdx.y * 128;
  const int tid = threadIdx.x;
  const int lane = tid & 31;
  const int wid = tid >> 5;
  const int wm = wid & 3;
  const int wn = wid >> 2;
  const int g = lane >> 2;
  const int t4 = lane & 3;

  const int lrow = tid >> 2;
  const int c4 = tid & 3;

  const int l15 = lane & 15;
  const int kh = (lane >> 4) * 16;
  const int e8 = ((lane >> 3) & 1) * 8;
  const int l7 = lane & 7;

#pragma unroll
  for (int p = 0; p < 2; p++) {
    int row = lrow + p * 64;
    cp16(as_b + row * QROW + c4 * 16, &X[(m0 + row) * E_ + c4 * 8]);
    cp16(bs_b + row * QROW + c4 * 16, &W[(e0 + row) * E_ + c4 * 8]);
  }
  cp_commit();

  float acc[2][8][4] = {};

  for (int k0 = 0; k0 < E_; k0 += 32) {
    const int cur = (k0 >> 5) & 1;
    cp_wait0();
    __syncthreads();

    if (k0 + 32 < E_) {
      const int nxt = cur ^ 1;
#pragma unroll
      for (int p = 0; p < 2; p++) {
        int row = lrow + p * 64;
        cp16(as_b + nxt * QBUF + row * QROW + c4 * 16,
             &X[(m0 + row) * E_ + k0 + 32 + c4 * 8]);
        cp16(bs_b + nxt * QBUF + row * QROW + c4 * 16,
             &W[(e0 + row) * E_ + k0 + 32 + c4 * 8]);
      }
      cp_commit();
    }

    const uint32_t ab = as_b + cur * QBUF;
    const uint32_t bb = bs_b + cur * QBUF;

#pragma unroll
    for (int ks = 0; ks < 2; ks++) {
      uint32_t a[2][4];
#pragma unroll
      for (int i = 0; i < 2; i++)
        ldsm4(a[i][0], a[i][1], a[i][2], a[i][3],
              ab + (wm * 32 + i * 16 + l15) * QROW + ks * 32 + kh);
#pragma unroll
      for (int jp = 0; jp < 4; jp++) {
        uint32_t b0, b1, b2, b3;
        ldsm4(b0, b1, b2, b3,
              bb + (wn * 64 + jp * 16 + e8 + l7) * QROW + ks * 32 + kh);
#pragma unroll
        for (int i = 0; i < 2; i++) {
          mmaf16(acc[i][2 * jp],     a[i][0], a[i][1], a[i][2], a[i][3], b0, b2);
          mmaf16(acc[i][2 * jp + 1], a[i][0], a[i][1], a[i][2], a[i][3], b1, b3);
        }
      }
    }
  }

  // Epilogue: half2 stores into [nh][t][d] (fp16); Q pre-scaled.
  const int h = (e0 >> 6) + wn;
#pragma unroll
  for (int i = 0; i < 2; i++) {
#pragma unroll
    for (int j = 0; j < 8; j++) {
      int d = j * 8 + 2 * t4;
      int m = m0 + wm * 32 + i * 16 + g;
#pragma unroll
      for (int half = 0; half < 2; half++) {
        int mm = m + half * 8;
        int n = mm >> 11, tt = mm & (T_ - 1);
        uint32_t hv = pack2(acc[i][j][2 * half] * osc,
                            acc[i][j][2 * half + 1] * osc);
        *reinterpret_cast<uint32_t*>(
            &out[((size_t)(n * H_ + h) * T_ + tt) * D_ + d]) = hv;
      }
    }
  }
}

// ---------------------------------------------------------------------------
// Flash attention fp16 m16n8k16. Br=128, Bc=64, 4 warps, warp M=32.
// Q pre-scaled -> S comes out in log2 domain directly (no per-element mul).
// P packed to half2 right after softmax (frees sacc regs) -> 3 CTAs/SM.
// ---------------------------------------------------------------------------
#define ASTH 72      // halfs
#define AROW 144     // bytes
#define KVBUF (64*AROW)

__global__ __launch_bounds__(128, 3) void attn_kernel(float* __restrict__ out) {
  extern __shared__ __half smh[];
  const uint32_t sbase = (uint32_t)__cvta_generic_to_shared(smh);
  const uint32_t qs_b = sbase;                       // [128][72h]
  const uint32_t ks_b = sbase + 128 * AROW;          // [2][64][72h]
  const uint32_t vs_b = ks_b + 2 * KVBUF;            // [2][64][72h]

  const int qb = blockIdx.x;
  const int nh = blockIdx.y;
  const __half* __restrict__ Qg = g_q + (size_t)nh * T_ * D_ + (size_t)qb * 128 * D_;
  const __half* __restrict__ Kg = g_k + (size_t)nh * T_ * D_;
  const __half* __restrict__ Vg = g_v + (size_t)nh * T_ * D_;

  const int tid = threadIdx.x;
  const int lane = tid & 31;
  const int wid = tid >> 5;           // 0..3
  const int g = lane >> 2;
  const int t4 = lane & 3;
  const int wbase = wid * 32;

  const int lrow = tid >> 3;
  const int c8 = tid & 7;

  const int l15 = lane & 15;
  const int kh = (lane >> 4) * 16;
  const int e8 = ((lane >> 3) & 1) * 8;
  const int l7 = lane & 7;

#pragma unroll
  for (int p = 0; p < 8; p++) {
    int row = lrow + p * 16;
    cp16(qs_b + row * AROW + c8 * 16, &Qg[row * D_ + c8 * 8]);
  }
#pragma unroll
  for (int p = 0; p < 4; p++) {
    int row = lrow + p * 16;
    cp16(ks_b + row * AROW + c8 * 16, &Kg[row * D_ + c8 * 8]);
    cp16(vs_b + row * AROW + c8 * 16, &Vg[row * D_ + c8 * 8]);
  }
  cp_commit();

  float o[2][8][4] = {};
  float mi[4], li[4];
#pragma unroll
  for (int s = 0; s < 4; s++) { mi[s] = -CUDART_INF_F; li[s] = 0.f; }

  for (int kb = 0; kb < T_ / 64; kb++) {
    const int cur = kb & 1;
    cp_wait0();
    __syncthreads();

    if (kb + 1 < T_ / 64) {
      const int nxt = cur ^ 1;
      const size_t gbase = (size_t)(kb + 1) * 64;
#pragma unroll
      for (int p = 0; p < 4; p++) {
        int row = lrow + p * 16;
        cp16(ks_b + nxt * KVBUF + row * AROW + c8 * 16,
             &Kg[(gbase + row) * D_ + c8 * 8]);
        cp16(vs_b + nxt * KVBUF + row * AROW + c8 * 16,
             &Vg[(gbase + row) * D_ + c8 * 8]);
      }
      cp_commit();
    }

    const uint32_t kbuf = ks_b + cur * KVBUF;
    const uint32_t vbuf = vs_b + cur * KVBUF;

    // ---- S = Q @ K^T (already in log2 domain via pre-scaled Q) ----
    float sacc[2][8][4] = {};
#pragma unroll
    for (int ks = 0; ks < 4; ks++) {
      uint32_t a[2][4];
#pragma unroll
      for (int i = 0; i < 2; i++)
        ldsm4(a[i][0], a[i][1], a[i][2], a[i][3],
              qs_b + (wbase + i * 16 + l15) * AROW + ks * 32 + kh);
#pragma unroll
      for (int jp = 0; jp < 4; jp++) {
        uint32_t b0, b1, b2, b3;
        ldsm4(b0, b1, b2, b3,
              kbuf + (jp * 16 + e8 + l7) * AROW + ks * 32 + kh);
#pragma unroll
        for (int i = 0; i < 2; i++) {
          mmaf16(sacc[i][2 * jp],     a[i][0], a[i][1], a[i][2], a[i][3], b0, b2);
          mmaf16(sacc[i][2 * jp + 1], a[i][0], a[i][1], a[i][2], a[i][3], b1, b3);
        }
      }
    }

    // ---- online softmax (log2 domain): 4 row-slots per thread ----
#pragma unroll
    for (int i = 0; i < 2; i++) {
#pragma unroll
      for (int rh = 0; rh < 2; rh++) {
        const int s = i * 2 + rh;
        float mx = -CUDART_INF_F;
#pragma unroll
        for (int j = 0; j < 8; j++)
          mx = fmaxf(mx, fmaxf(sacc[i][j][2 * rh], sacc[i][j][2 * rh + 1]));
        mx = fmaxf(mx, __shfl_xor_sync(0xffffffffu, mx, 1));
        mx = fmaxf(mx, __shfl_xor_sync(0xffffffffu, mx, 2));
        float mnew = fmaxf(mi[s], mx);
        float alpha = ex2(mi[s] - mnew);
        float rs = 0.f;
#pragma unroll
        for (int j = 0; j < 8; j++) {
          sacc[i][j][2 * rh]     = ex2(sacc[i][j][2 * rh] - mnew);
          sacc[i][j][2 * rh + 1] = ex2(sacc[i][j][2 * rh + 1] - mnew);
          rs += sacc[i][j][2 * rh] + sacc[i][j][2 * rh + 1];
        }
        rs += __shfl_xor_sync(0xffffffffu, rs, 1);
        rs += __shfl_xor_sync(0xffffffffu, rs, 2);
        li[s] = li[s] * alpha + rs;
        mi[s] = mnew;
#pragma unroll
        for (int j = 0; j < 8; j++) {
          o[i][j][2 * rh]     *= alpha;
          o[i][j][2 * rh + 1] *= alpha;
        }
      }
    }

    // ---- pack P to half2 now (sacc dead afterwards -> fewer live regs) ----
    uint32_t pah[2][4][4];
#pragma unroll
    for (int i = 0; i < 2; i++) {
#pragma unroll
      for (int ks2 = 0; ks2 < 4; ks2++) {
        pah[i][ks2][0] = pack2(sacc[i][2 * ks2][0],     sacc[i][2 * ks2][1]);
        pah[i][ks2][1] = pack2(sacc[i][2 * ks2][2],     sacc[i][2 * ks2][3]);
        pah[i][ks2][2] = pack2(sacc[i][2 * ks2 + 1][0], sacc[i][2 * ks2 + 1][1]);
        pah[i][ks2][3] = pack2(sacc[i][2 * ks2 + 1][2], sacc[i][2 * ks2 + 1][3]);
      }
    }

    // ---- O += P @ V : B via ldsm.trans ----
#pragma unroll
    for (int ks2 = 0; ks2 < 4; ks2++) {
#pragma unroll
      for (int jp = 0; jp < 4; jp++) {
        uint32_t v0, v1, v2, v3;
        ldsm4t(v0, v1, v2, v3,
               vbuf + (ks2 * 16 + e8 + l7) * AROW + jp * 32 + kh);
#pragma unroll
        for (int i = 0; i < 2; i++) {
          mmaf16(o[i][2 * jp],     pah[i][ks2][0], pah[i][ks2][1],
                 pah[i][ks2][2], pah[i][ks2][3], v0, v1);
          mmaf16(o[i][2 * jp + 1], pah[i][ks2][0], pah[i][ks2][1],
                 pah[i][ks2][2], pah[i][ks2][3], v2, v3);
        }
      }
    }
  }

  // ---- epilogue (fp32 output, natural layout) ----
  const int n = nh / H_;
  const int h = nh - n * H_;
#pragma unroll
  for (int i = 0; i < 2; i++) {
#pragma unroll
    for (int rh = 0; rh < 2; rh++) {
      float inv = 1.f / li[i * 2 + rh];
      int t = qb * 128 + wbase + i * 16 + rh * 8 + g;
#pragma unroll
      for (int j = 0; j < 8; j++) {
        int d = j * 8 + 2 * t4;
        *reinterpret_cast<float2*>(
            &out[((size_t)n * T_ + t) * E_ + h * D_ + d]) =
            make_float2(o[i][j][2 * rh] * inv, o[i][j][2 * rh + 1] * inv);
      }
    }
  }
}

extern "C" void kernel_launch(void* const* d_in, const int* in_sizes, int n_in,
                              void* d_out, int out_size) {
  const float* x  = (const float*)d_in[0];
  const float* Wq = (const float*)d_in[1];
  const float* Wk = (const float*)d_in[2];
  const float* Wv = (const float*)d_in[3];
  float* out = (float*)d_out;

  round_kernel<<<(TOT4 + 255) / 256, 256>>>(x, Wq, Wk, Wv);

  const int qkv_smem = 4 * QBUF;   // 40960 B
  cudaFuncSetAttribute(qkv_kernel, cudaFuncAttributeMaxDynamicSharedMemorySize,
                       qkv_smem);
  dim3 gq(NT_ / 128, E_ / 128, 3);
  qkv_kernel<<<gq, 256, qkv_smem>>>();

  const int attn_smem = 128 * AROW + 4 * KVBUF;  // 55296 B
  cudaFuncSetAttribute(attn_kernel, cudaFuncAttributeMaxDynamicSharedMemorySize,
                       attn_smem);
  dim3 ga(T_ / 128, NH_);
  attn_kernel<<<ga, 128, attn_smem>>>(out);
}

// round 12
// speedup vs baseline: 2.2422x; 1.0387x over previous
#include <cuda_runtime.h>
#include <cuda_fp16.h>
#include <math_constants.h>
#include <cstdint>

// Problem constants
#define N_ 4
#define T_ 2048
#define E_ 768
#define H_ 12
#define D_ 64
#define NT_ (N_*T_)    // 8192
#define NH_ (N_*H_)    // 48
#define EE_ (E_*E_)    // 589824

// Scratch (fp16). Q is pre-scaled by 1/sqrt(D)*log2(e).
__device__ __half g_q[NH_*T_*D_];
__device__ __half g_k[NH_*T_*D_];
__device__ __half g_v[NH_*T_*D_];
__device__ __half g_xh[NT_*E_];
__device__ __half g_wh[3*EE_];

__device__ __forceinline__ float ex2(float x) {
  float y;
  asm("ex2.approx.f32 %0, %1;" : "=f"(y) : "f"(x));
  return y;
}
__device__ __forceinline__ uint32_t ex2h2(uint32_t x) {
  uint32_t y;
  asm("ex2.approx.f16x2 %0, %1;" : "=r"(y) : "r"(x));
  return y;
}
__device__ __forceinline__ uint32_t pack2(float lo, float hi) {
  uint32_t r;
  asm("cvt.rn.f16x2.f32 %0, %1, %2;" : "=r"(r) : "f"(hi), "f"(lo));
  return r;
}

// D = A*B + D, m16n8k16 f16 in, f32 accum
__device__ __forceinline__ void mmaf16(float* c, uint32_t a0, uint32_t a1,
                                       uint32_t a2, uint32_t a3,
                                       uint32_t b0, uint32_t b1) {
  asm volatile(
      "mma.sync.aligned.m16n8k16.row.col.f32.f16.f16.f32 "
      "{%0,%1,%2,%3},{%4,%5,%6,%7},{%8,%9},{%0,%1,%2,%3};"
      : "+f"(c[0]), "+f"(c[1]), "+f"(c[2]), "+f"(c[3])
      : "r"(a0), "r"(a1), "r"(a2), "r"(a3), "r"(b0), "r"(b1));
}

__device__ __forceinline__ void ldsm4(uint32_t& r0, uint32_t& r1, uint32_t& r2,
                                      uint32_t& r3, uint32_t addr) {
  asm volatile("ldmatrix.sync.aligned.m8n8.x4.shared.b16 {%0,%1,%2,%3}, [%4];"
               : "=r"(r0), "=r"(r1), "=r"(r2), "=r"(r3) : "r"(addr));
}
__device__ __forceinline__ void ldsm4t(uint32_t& r0, uint32_t& r1, uint32_t& r2,
                                       uint32_t& r3, uint32_t addr) {
  asm volatile("ldmatrix.sync.aligned.m8n8.x4.trans.shared.b16 {%0,%1,%2,%3}, [%4];"
               : "=r"(r0), "=r"(r1), "=r"(r2), "=r"(r3) : "r"(addr));
}

__device__ __forceinline__ void cp16(uint32_t smem_addr, const void* gptr) {
  asm volatile("cp.async.cg.shared.global [%0], [%1], 16;"
               :: "r"(smem_addr), "l"(gptr));
}
__device__ __forceinline__ void cp_commit() {
  asm volatile("cp.async.commit_group;");
}
__device__ __forceinline__ void cp_wait0() {
  asm volatile("cp.async.wait_group 0;");
}

// ---------------------------------------------------------------------------
// Convert x,Wq,Wk,Wv fp32 -> fp16, one merged launch.
// ---------------------------------------------------------------------------
#define XQ4 (NT_*E_/4)   // 1572864
#define WQ4 (EE_/4)      // 147456
#define TOT4 (XQ4 + 3*WQ4)

__global__ __launch_bounds__(256) void round_kernel(
    const float* __restrict__ x, const float* __restrict__ wq,
    const float* __restrict__ wk, const float* __restrict__ wv) {
  int i = blockIdx.x * 256 + threadIdx.x;
  if (i >= TOT4) return;
  const float* src;
  __half* dst;
  int li;
  if (i < XQ4)            { src = x;  dst = g_xh;         li = i; }
  else if (i < XQ4+WQ4)   { src = wq; dst = g_wh;         li = i - XQ4; }
  else if (i < XQ4+2*WQ4) { src = wk; dst = g_wh + EE_;   li = i - XQ4 - WQ4; }
  else                    { src = wv; dst = g_wh + 2*EE_; li = i - XQ4 - 2*WQ4; }
  float4 v = reinterpret_cast<const float4*>(src)[li];
  uint2 h;
  h.x = pack2(v.x, v.y);
  h.y = pack2(v.z, v.w);
  reinterpret_cast<uint2*>(dst)[li] = h;
}

// ---------------------------------------------------------------------------
// QKV projection (fp16 m16n8k16): out[m][e] = sum_k x[m][k]*W[e][k]
// CTA 128x128, BK=32 double-buffered cp.async, 8 warps (wm4 x wn2), warp 32x64.
// smem rows: 32 halfs + 8 pad = 40 halfs = 80B (ldsm conflict-free).
// Q output pre-scaled by 1/sqrt(D)*log2(e) so attn softmax needs no scaling.
// ---------------------------------------------------------------------------
#define QSTH 40   // halfs
#define QROW 80   // bytes
#define QBUF (128*QROW)

__global__ __launch_bounds__(256, 2) void qkv_kernel() {
  extern __shared__ __half smh[];
  const uint32_t sbase = (uint32_t)__cvta_generic_to_shared(smh);
  const uint32_t as_b = sbase;                 // [2][128][40h]
  const uint32_t bs_b = sbase + 2 * QBUF;      // [2][128][40h]

  const int which = blockIdx.z;
  const __half* __restrict__ X = g_xh;
  const __half* __restrict__ W = g_wh + which * EE_;
  __half* __restrict__ out = (which == 0) ? g_q : ((which == 1) ? g_k : g_v);
  const float osc = (which == 0) ? 0.18033688011111793f : 1.0f;  // 0.125*log2e

  const int m0 = blockIdx.x * 128;
  const int e0 = blockIdx.y * 128;
  const int tid = threadIdx.x;
  const int lane = tid & 31;
  const int wid = tid >> 5;
  const int wm = wid & 3;
  const int wn = wid >> 2;
  const int g = lane >> 2;
  const int t4 = lane & 3;

  const int lrow = tid >> 2;
  const int c4 = tid & 3;

  const int l15 = lane & 15;
  const int kh = (lane >> 4) * 16;
  const int e8 = ((lane >> 3) & 1) * 8;
  const int l7 = lane & 7;

#pragma unroll
  for (int p = 0; p < 2; p++) {
    int row = lrow + p * 64;
    cp16(as_b + row * QROW + c4 * 16, &X[(m0 + row) * E_ + c4 * 8]);
    cp16(bs_b + row * QROW + c4 * 16, &W[(e0 + row) * E_ + c4 * 8]);
  }
  cp_commit();

  float acc[2][8][4] = {};

  for (int k0 = 0; k0 < E_; k0 += 32) {
    const int cur = (k0 >> 5) & 1;
    cp_wait0();
    __syncthreads();

    if (k0 + 32 < E_) {
      const int nxt = cur ^ 1;
#pragma unroll
      for (int p = 0; p < 2; p++) {
        int row = lrow + p * 64;
        cp16(as_b + nxt * QBUF + row * QROW + c4 * 16,
             &X[(m0 + row) * E_ + k0 + 32 + c4 * 8]);
        cp16(bs_b + nxt * QBUF + row * QROW + c4 * 16,
             &W[(e0 + row) * E_ + k0 + 32 + c4 * 8]);
      }
      cp_commit();
    }

    const uint32_t ab = as_b + cur * QBUF;
    const uint32_t bb = bs_b + cur * QBUF;

#pragma unroll
    for (int ks = 0; ks < 2; ks++) {
      uint32_t a[2][4];
#pragma unroll
      for (int i = 0; i < 2; i++)
        ldsm4(a[i][0], a[i][1], a[i][2], a[i][3],
              ab + (wm * 32 + i * 16 + l15) * QROW + ks * 32 + kh);
#pragma unroll
      for (int jp = 0; jp < 4; jp++) {
        uint32_t b0, b1, b2, b3;
        ldsm4(b0, b1, b2, b3,
              bb + (wn * 64 + jp * 16 + e8 + l7) * QROW + ks * 32 + kh);
#pragma unroll
        for (int i = 0; i < 2; i++) {
          mmaf16(acc[i][2 * jp],     a[i][0], a[i][1], a[i][2], a[i][3], b0, b2);
          mmaf16(acc[i][2 * jp + 1], a[i][0], a[i][1], a[i][2], a[i][3], b1, b3);
        }
      }
    }
  }

  // Epilogue: half2 stores into [nh][t][d] (fp16); Q pre-scaled.
  const int h = (e0 >> 6) + wn;
#pragma unroll
  for (int i = 0; i < 2; i++) {
#pragma unroll
    for (int j = 0; j < 8; j++) {
      int d = j * 8 + 2 * t4;
      int m = m0 + wm * 32 + i * 16 + g;
#pragma unroll
      for (int half = 0; half < 2; half++) {
        int mm = m + half * 8;
        int n = mm >> 11, tt = mm & (T_ - 1);
        uint32_t hv = pack2(acc[i][j][2 * half] * osc,
                            acc[i][j][2 * half + 1] * osc);
        *reinterpret_cast<uint32_t*>(
            &out[((size_t)(n * H_ + h) * T_ + tt) * D_ + d]) = hv;
      }
    }
  }
}

// ---------------------------------------------------------------------------
// Flash attention fp16 m16n8k16. Br=128, Bc=64, 4 warps, warp M=32.
// Q pre-scaled -> S in log2 domain. exp via ex2.approx.f16x2 (packed, halves
// MUFU). Row sums via tensor core (P @ ones) -> no scalar adds/shuffles;
// li uses the SAME fp16 p as PV, so num/denom errors cancel to first order.
// ---------------------------------------------------------------------------
#define ASTH 72      // halfs
#define AROW 144     // bytes
#define KVBUF (64*AROW)

__global__ __launch_bounds__(128, 3) void attn_kernel(float* __restrict__ out) {
  extern __shared__ __half smh[];
  const uint32_t sbase = (uint32_t)__cvta_generic_to_shared(smh);
  const uint32_t qs_b = sbase;                       // [128][72h]
  const uint32_t ks_b = sbase + 128 * AROW;          // [2][64][72h]
  const uint32_t vs_b = ks_b + 2 * KVBUF;            // [2][64][72h]

  const int qb = blockIdx.x;
  const int nh = blockIdx.y;
  const __half* __restrict__ Qg = g_q + (size_t)nh * T_ * D_ + (size_t)qb * 128 * D_;
  const __half* __restrict__ Kg = g_k + (size_t)nh * T_ * D_;
  const __half* __restrict__ Vg = g_v + (size_t)nh * T_ * D_;

  const int tid = threadIdx.x;
  const int lane = tid & 31;
  const int wid = tid >> 5;           // 0..3
  const int g = lane >> 2;
  const int t4 = lane & 3;
  const int wbase = wid * 32;

  const int lrow = tid >> 3;
  const int c8 = tid & 7;

  const int l15 = lane & 15;
  const int kh = (lane >> 4) * 16;
  const int e8 = ((lane >> 3) & 1) * 8;
  const int l7 = lane & 7;

#pragma unroll
  for (int p = 0; p < 8; p++) {
    int row = lrow + p * 16;
    cp16(qs_b + row * AROW + c8 * 16, &Qg[row * D_ + c8 * 8]);
  }
#pragma unroll
  for (int p = 0; p < 4; p++) {
    int row = lrow + p * 16;
    cp16(ks_b + row * AROW + c8 * 16, &Kg[row * D_ + c8 * 8]);
    cp16(vs_b + row * AROW + c8 * 16, &Vg[row * D_ + c8 * 8]);
  }
  cp_commit();

  float o[2][8][4] = {};
  float mi[4], li[4];
#pragma unroll
  for (int s = 0; s < 4; s++) { mi[s] = -CUDART_INF_F; li[s] = 0.f; }

  const uint32_t ONE2 = 0x3C003C00u;   // half2(1,1)

  for (int kb = 0; kb < T_ / 64; kb++) {
    const int cur = kb & 1;
    cp_wait0();
    __syncthreads();

    if (kb + 1 < T_ / 64) {
      const int nxt = cur ^ 1;
      const size_t gbase = (size_t)(kb + 1) * 64;
#pragma unroll
      for (int p = 0; p < 4; p++) {
        int row = lrow + p * 16;
        cp16(ks_b + nxt * KVBUF + row * AROW + c8 * 16,
             &Kg[(gbase + row) * D_ + c8 * 8]);
        cp16(vs_b + nxt * KVBUF + row * AROW + c8 * 16,
             &Vg[(gbase + row) * D_ + c8 * 8]);
      }
      cp_commit();
    }

    const uint32_t kbuf = ks_b + cur * KVBUF;
    const uint32_t vbuf = vs_b + cur * KVBUF;

    // ---- S = Q @ K^T (log2 domain) ----
    float sacc[2][8][4] = {};
#pragma unroll
    for (int ks = 0; ks < 4; ks++) {
      uint32_t a[2][4];
#pragma unroll
      for (int i = 0; i < 2; i++)
        ldsm4(a[i][0], a[i][1], a[i][2], a[i][3],
              qs_b + (wbase + i * 16 + l15) * AROW + ks * 32 + kh);
#pragma unroll
      for (int jp = 0; jp < 4; jp++) {
        uint32_t b0, b1, b2, b3;
        ldsm4(b0, b1, b2, b3,
              kbuf + (jp * 16 + e8 + l7) * AROW + ks * 32 + kh);
#pragma unroll
        for (int i = 0; i < 2; i++) {
          mmaf16(sacc[i][2 * jp],     a[i][0], a[i][1], a[i][2], a[i][3], b0, b2);
          mmaf16(sacc[i][2 * jp + 1], a[i][0], a[i][1], a[i][2], a[i][3], b1, b3);
        }
      }
    }

    // ---- max-reduce + alpha + o rescale (per row-slot) ----
    float al[4];
#pragma unroll
    for (int i = 0; i < 2; i++) {
#pragma unroll
      for (int rh = 0; rh < 2; rh++) {
        const int s = i * 2 + rh;
        float mx = -CUDART_INF_F;
#pragma unroll
        for (int j = 0; j < 8; j++)
          mx = fmaxf(mx, fmaxf(sacc[i][j][2 * rh], sacc[i][j][2 * rh + 1]));
        mx = fmaxf(mx, __shfl_xor_sync(0xffffffffu, mx, 1));
        mx = fmaxf(mx, __shfl_xor_sync(0xffffffffu, mx, 2));
        float mnew = fmaxf(mi[s], mx);
        al[s] = ex2(mi[s] - mnew);
        mi[s] = mnew;
#pragma unroll
        for (int j = 0; j < 8; j++) {
          o[i][j][2 * rh]     *= al[s];
          o[i][j][2 * rh + 1] *= al[s];
        }
      }
    }

    // ---- p = 2^(s - m) in packed fp16 (PV A-fragment layout) ----
    uint32_t pah[2][4][4];
#pragma unroll
    for (int i = 0; i < 2; i++) {
      const float m0f = mi[i * 2], m1f = mi[i * 2 + 1];
#pragma unroll
      for (int ks2 = 0; ks2 < 4; ks2++) {
        pah[i][ks2][0] = ex2h2(pack2(sacc[i][2 * ks2][0] - m0f,
                                     sacc[i][2 * ks2][1] - m0f));
        pah[i][ks2][1] = ex2h2(pack2(sacc[i][2 * ks2][2] - m1f,
                                     sacc[i][2 * ks2][3] - m1f));
        pah[i][ks2][2] = ex2h2(pack2(sacc[i][2 * ks2 + 1][0] - m0f,
                                     sacc[i][2 * ks2 + 1][1] - m0f));
        pah[i][ks2][3] = ex2h2(pack2(sacc[i][2 * ks2 + 1][2] - m1f,
                                     sacc[i][2 * ks2 + 1][3] - m1f));
      }
    }

    // ---- O += P @ V ; rsum += P @ ones (row sums on tensor core) ----
    float rsum[2][4] = {};
#pragma unroll
    for (int ks2 = 0; ks2 < 4; ks2++) {
#pragma unroll
      for (int jp = 0; jp < 4; jp++) {
        uint32_t v0, v1, v2, v3;
        ldsm4t(v0, v1, v2, v3,
               vbuf + (ks2 * 16 + e8 + l7) * AROW + jp * 32 + kh);
#pragma unroll
        for (int i = 0; i < 2; i++) {
          mmaf16(o[i][2 * jp],     pah[i][ks2][0], pah[i][ks2][1],
                 pah[i][ks2][2], pah[i][ks2][3], v0, v1);
          mmaf16(o[i][2 * jp + 1], pah[i][ks2][0], pah[i][ks2][1],
                 pah[i][ks2][2], pah[i][ks2][3], v2, v3);
        }
      }
#pragma unroll
      for (int i = 0; i < 2; i++)
        mmaf16(rsum[i], pah[i][ks2][0], pah[i][ks2][1],
               pah[i][ks2][2], pah[i][ks2][3], ONE2, ONE2);
    }

    // ---- deferred li update (every thread has its rows' sums in c0/c2) ----
#pragma unroll
    for (int i = 0; i < 2; i++) {
#pragma unroll
      for (int rh = 0; rh < 2; rh++) {
        const int s = i * 2 + rh;
        li[s] = li[s] * al[s] + rsum[i][2 * rh];
      }
    }
  }

  // ---- epilogue (fp32 output, natural layout) ----
  const int n = nh / H_;
  const int h = nh - n * H_;
#pragma unroll
  for (int i = 0; i < 2; i++) {
#pragma unroll
    for (int rh = 0; rh < 2; rh++) {
      float inv = 1.f / li[i * 2 + rh];
      int t = qb * 128 + wbase + i * 16 + rh * 8 + g;
#pragma unroll
      for (int j = 0; j < 8; j++) {
        int d = j * 8 + 2 * t4;
        *reinterpret_cast<float2*>(
            &out[((size_t)n * T_ + t) * E_ + h * D_ + d]) =
            make_float2(o[i][j][2 * rh] * inv, o[i][j][2 * rh + 1] * inv);
      }
    }
  }
}

extern "C" void kernel_launch(void* const* d_in, const int* in_sizes, int n_in,
                              void* d_out, int out_size) {
  const float* x  = (const float*)d_in[0];
  const float* Wq = (const float*)d_in[1];
  const float* Wk = (const float*)d_in[2];
  const float* Wv = (const float*)d_in[3];
  float* out = (float*)d_out;

  round_kernel<<<(TOT4 + 255) / 256, 256>>>(x, Wq, Wk, Wv);

  const int qkv_smem = 4 * QBUF;   // 40960 B
  cudaFuncSetAttribute(qkv_kernel, cudaFuncAttributeMaxDynamicSharedMemorySize,
                       qkv_smem);
  dim3 gq(NT_ / 128, E_ / 128, 3);
  qkv_kernel<<<gq, 256, qkv_smem>>>();

  const int attn_smem = 128 * AROW + 4 * KVBUF;  // 55296 B
  cudaFuncSetAttribute(attn_kernel, cudaFuncAttributeMaxDynamicSharedMemorySize,
                       attn_smem);
  dim3 ga(T_ / 128, NH_);
  attn_kernel<<<ga, 128, attn_smem>>>(out);
}

// round 13
// speedup vs baseline: 2.2606x; 1.0082x over previous
#include <cuda_runtime.h>
#include <cuda_fp16.h>
#include <math_constants.h>
#include <cstdint>

// Problem constants
#define N_ 4
#define T_ 2048
#define E_ 768
#define H_ 12
#define D_ 64
#define NT_ (N_*T_)    // 8192
#define NH_ (N_*H_)    // 48
#define EE_ (E_*E_)    // 589824

// Scratch (fp16). Q is pre-scaled by 1/sqrt(D)*log2(e).
__device__ __half g_q[NH_*T_*D_];
__device__ __half g_k[NH_*T_*D_];
__device__ __half g_v[NH_*T_*D_];
__device__ __half g_xh[NT_*E_];
__device__ __half g_wh[3*EE_];

__device__ __forceinline__ float ex2(float x) {
  float y;
  asm("ex2.approx.f32 %0, %1;" : "=f"(y) : "f"(x));
  return y;
}
__device__ __forceinline__ uint32_t ex2h2(uint32_t x) {
  uint32_t y;
  asm("ex2.approx.f16x2 %0, %1;" : "=r"(y) : "r"(x));
  return y;
}
__device__ __forceinline__ uint32_t pack2(float lo, float hi) {
  uint32_t r;
  asm("cvt.rn.f16x2.f32 %0, %1, %2;" : "=r"(r) : "f"(hi), "f"(lo));
  return r;
}

// D = A*B + D, m16n8k16 f16 in, f32 accum
__device__ __forceinline__ void mmaf16(float* c, uint32_t a0, uint32_t a1,
                                       uint32_t a2, uint32_t a3,
                                       uint32_t b0, uint32_t b1) {
  asm volatile(
      "mma.sync.aligned.m16n8k16.row.col.f32.f16.f16.f32 "
      "{%0,%1,%2,%3},{%4,%5,%6,%7},{%8,%9},{%0,%1,%2,%3};"
      : "+f"(c[0]), "+f"(c[1]), "+f"(c[2]), "+f"(c[3])
      : "r"(a0), "r"(a1), "r"(a2), "r"(a3), "r"(b0), "r"(b1));
}

__device__ __forceinline__ void ldsm4(uint32_t& r0, uint32_t& r1, uint32_t& r2,
                                      uint32_t& r3, uint32_t addr) {
  asm volatile("ldmatrix.sync.aligned.m8n8.x4.shared.b16 {%0,%1,%2,%3}, [%4];"
               : "=r"(r0), "=r"(r1), "=r"(r2), "=r"(r3) : "r"(addr));
}
__device__ __forceinline__ void ldsm4t(uint32_t& r0, uint32_t& r1, uint32_t& r2,
                                       uint32_t& r3, uint32_t addr) {
  asm volatile("ldmatrix.sync.aligned.m8n8.x4.trans.shared.b16 {%0,%1,%2,%3}, [%4];"
               : "=r"(r0), "=r"(r1), "=r"(r2), "=r"(r3) : "r"(addr));
}

__device__ __forceinline__ void cp16(uint32_t smem_addr, const void* gptr) {
  asm volatile("cp.async.cg.shared.global [%0], [%1], 16;"
               :: "r"(smem_addr), "l"(gptr));
}
__device__ __forceinline__ void cp_commit() {
  asm volatile("cp.async.commit_group;");
}
__device__ __forceinline__ void cp_wait0() {
  asm volatile("cp.async.wait_group 0;");
}

// ---------------------------------------------------------------------------
// Convert x,Wq,Wk,Wv fp32 -> fp16, one merged launch.
// ---------------------------------------------------------------------------
#define XQ4 (NT_*E_/4)   // 1572864
#define WQ4 (EE_/4)      // 147456
#define TOT4 (XQ4 + 3*WQ4)

__global__ __launch_bounds__(256) void round_kernel(
    const float* __restrict__ x, const float* __restrict__ wq,
    const float* __restrict__ wk, const float* __restrict__ wv) {
  int i = blockIdx.x * 256 + threadIdx.x;
  if (i >= TOT4) return;
  const float* src;
  __half* dst;
  int li;
  if (i < XQ4)            { src = x;  dst = g_xh;         li = i; }
  else if (i < XQ4+WQ4)   { src = wq; dst = g_wh;         li = i - XQ4; }
  else if (i < XQ4+2*WQ4) { src = wk; dst = g_wh + EE_;   li = i - XQ4 - WQ4; }
  else                    { src = wv; dst = g_wh + 2*EE_; li = i - XQ4 - 2*WQ4; }
  float4 v = reinterpret_cast<const float4*>(src)[li];
  uint2 h;
  h.x = pack2(v.x, v.y);
  h.y = pack2(v.z, v.w);
  reinterpret_cast<uint2*>(dst)[li] = h;
}

// ---------------------------------------------------------------------------
// QKV projection (fp16 m16n8k16): out[m][e] = sum_k x[m][k]*W[e][k]
// CTA 128x128, BK=64 double-buffered cp.async (half the barriers of BK=32),
// 8 warps (wm4 x wn2), warp 32x64.
// smem rows: 64 halfs + 8 pad = 72 halfs = 144B (ldsm groups 9r mod 8 -> CF).
// Q output pre-scaled by 1/sqrt(D)*log2(e) so attn softmax needs no scaling.
// ---------------------------------------------------------------------------
#define QROW 144            // bytes per row (64h data + 8h pad)
#define QBUF (128*QROW)     // 18432 B per buffer

__global__ __launch_bounds__(256, 2) void qkv_kernel() {
  extern __shared__ __half smh[];
  const uint32_t sbase = (uint32_t)__cvta_generic_to_shared(smh);
  const uint32_t as_b = sbase;                 // [2][128][72h]
  const uint32_t bs_b = sbase + 2 * QBUF;      // [2][128][72h]

  const int which = blockIdx.z;
  const __half* __restrict__ X = g_xh;
  const __half* __restrict__ W = g_wh + which * EE_;
  __half* __restrict__ out = (which == 0) ? g_q : ((which == 1) ? g_k : g_v);
  const float osc = (which == 0) ? 0.18033688011111793f : 1.0f;  // 0.125*log2e

  const int m0 = blockIdx.x * 128;
  const int e0 = blockIdx.y * 128;
  const int tid = threadIdx.x;
  const int lane = tid & 31;
  const int wid = tid >> 5;
  const int wm = wid & 3;
  const int wn = wid >> 2;
  const int g = lane >> 2;
  const int t4 = lane & 3;

  // loader: row = (tid>>3)+p*32 (4 passes), 16B chunk = tid&7 (covers 128B)
  const int lrow = tid >> 3;
  const int c8 = tid & 7;

  const int l15 = lane & 15;
  const int kh = (lane >> 4) * 16;
  const int e8 = ((lane >> 3) & 1) * 8;
  const int l7 = lane & 7;

#pragma unroll
  for (int p = 0; p < 4; p++) {
    int row = lrow + p * 32;
    cp16(as_b + row * QROW + c8 * 16, &X[(m0 + row) * E_ + c8 * 8]);
    cp16(bs_b + row * QROW + c8 * 16, &W[(e0 + row) * E_ + c8 * 8]);
  }
  cp_commit();

  float acc[2][8][4] = {};

  for (int k0 = 0; k0 < E_; k0 += 64) {
    const int cur = (k0 >> 6) & 1;
    cp_wait0();
    __syncthreads();

    if (k0 + 64 < E_) {
      const int nxt = cur ^ 1;
#pragma unroll
      for (int p = 0; p < 4; p++) {
        int row = lrow + p * 32;
        cp16(as_b + nxt * QBUF + row * QROW + c8 * 16,
             &X[(m0 + row) * E_ + k0 + 64 + c8 * 8]);
        cp16(bs_b + nxt * QBUF + row * QROW + c8 * 16,
             &W[(e0 + row) * E_ + k0 + 64 + c8 * 8]);
      }
      cp_commit();
    }

    const uint32_t ab = as_b + cur * QBUF;
    const uint32_t bb = bs_b + cur * QBUF;

#pragma unroll
    for (int ks = 0; ks < 4; ks++) {
      uint32_t a[2][4];
#pragma unroll
      for (int i = 0; i < 2; i++)
        ldsm4(a[i][0], a[i][1], a[i][2], a[i][3],
              ab + (wm * 32 + i * 16 + l15) * QROW + ks * 32 + kh);
#pragma unroll
      for (int jp = 0; jp < 4; jp++) {
        uint32_t b0, b1, b2, b3;
        ldsm4(b0, b1, b2, b3,
              bb + (wn * 64 + jp * 16 + e8 + l7) * QROW + ks * 32 + kh);
#pragma unroll
        for (int i = 0; i < 2; i++) {
          mmaf16(acc[i][2 * jp],     a[i][0], a[i][1], a[i][2], a[i][3], b0, b2);
          mmaf16(acc[i][2 * jp + 1], a[i][0], a[i][1], a[i][2], a[i][3], b1, b3);
        }
      }
    }
  }

  // Epilogue: half2 stores into [nh][t][d] (fp16); Q pre-scaled.
  const int h = (e0 >> 6) + wn;
#pragma unroll
  for (int i = 0; i < 2; i++) {
#pragma unroll
    for (int j = 0; j < 8; j++) {
      int d = j * 8 + 2 * t4;
      int m = m0 + wm * 32 + i * 16 + g;
#pragma unroll
      for (int half = 0; half < 2; half++) {
        int mm = m + half * 8;
        int n = mm >> 11, tt = mm & (T_ - 1);
        uint32_t hv = pack2(acc[i][j][2 * half] * osc,
                            acc[i][j][2 * half + 1] * osc);
        *reinterpret_cast<uint32_t*>(
            &out[((size_t)(n * H_ + h) * T_ + tt) * D_ + d]) = hv;
      }
    }
  }
}

// ---------------------------------------------------------------------------
// Flash attention fp16 m16n8k16. Br=128, Bc=64, 4 warps, warp M=32.
// Q pre-scaled -> S in log2 domain. exp via ex2.approx.f16x2.
// Row sums on tensor core (P @ ones). Warp-uniform skip of the o-rescale
// when all 4 row-slot alphas are exactly 1 (common once maxima stabilize).
// ---------------------------------------------------------------------------
#define AROW 144     // bytes
#define KVBUF (64*AROW)

__global__ __launch_bounds__(128, 3) void attn_kernel(float* __restrict__ out) {
  extern __shared__ __half smh[];
  const uint32_t sbase = (uint32_t)__cvta_generic_to_shared(smh);
  const uint32_t qs_b = sbase;                       // [128][72h]
  const uint32_t ks_b = sbase + 128 * AROW;          // [2][64][72h]
  const uint32_t vs_b = ks_b + 2 * KVBUF;            // [2][64][72h]

  const int qb = blockIdx.x;
  const int nh = blockIdx.y;
  const __half* __restrict__ Qg = g_q + (size_t)nh * T_ * D_ + (size_t)qb * 128 * D_;
  const __half* __restrict__ Kg = g_k + (size_t)nh * T_ * D_;
  const __half* __restrict__ Vg = g_v + (size_t)nh * T_ * D_;

  const int tid = threadIdx.x;
  const int lane = tid & 31;
  const int wid = tid >> 5;           // 0..3
  const int g = lane >> 2;
  const int t4 = lane & 3;
  const int wbase = wid * 32;

  const int lrow = tid >> 3;
  const int c8 = tid & 7;

  const int l15 = lane & 15;
  const int kh = (lane >> 4) * 16;
  const int e8 = ((lane >> 3) & 1) * 8;
  const int l7 = lane & 7;

#pragma unroll
  for (int p = 0; p < 8; p++) {
    int row = lrow + p * 16;
    cp16(qs_b + row * AROW + c8 * 16, &Qg[row * D_ + c8 * 8]);
  }
#pragma unroll
  for (int p = 0; p < 4; p++) {
    int row = lrow + p * 16;
    cp16(ks_b + row * AROW + c8 * 16, &Kg[row * D_ + c8 * 8]);
    cp16(vs_b + row * AROW + c8 * 16, &Vg[row * D_ + c8 * 8]);
  }
  cp_commit();

  float o[2][8][4] = {};
  float mi[4], li[4];
#pragma unroll
  for (int s = 0; s < 4; s++) { mi[s] = -CUDART_INF_F; li[s] = 0.f; }

  const uint32_t ONE2 = 0x3C003C00u;   // half2(1,1)

  for (int kb = 0; kb < T_ / 64; kb++) {
    const int cur = kb & 1;
    cp_wait0();
    __syncthreads();

    if (kb + 1 < T_ / 64) {
      const int nxt = cur ^ 1;
      const size_t gbase = (size_t)(kb + 1) * 64;
#pragma unroll
      for (int p = 0; p < 4; p++) {
        int row = lrow + p * 16;
        cp16(ks_b + nxt * KVBUF + row * AROW + c8 * 16,
             &Kg[(gbase + row) * D_ + c8 * 8]);
        cp16(vs_b + nxt * KVBUF + row * AROW + c8 * 16,
             &Vg[(gbase + row) * D_ + c8 * 8]);
      }
      cp_commit();
    }

    const uint32_t kbuf = ks_b + cur * KVBUF;
    const uint32_t vbuf = vs_b + cur * KVBUF;

    // ---- S = Q @ K^T (log2 domain) ----
    float sacc[2][8][4] = {};
#pragma unroll
    for (int ks = 0; ks < 4; ks++) {
      uint32_t a[2][4];
#pragma unroll
      for (int i = 0; i < 2; i++)
        ldsm4(a[i][0], a[i][1], a[i][2], a[i][3],
              qs_b + (wbase + i * 16 + l15) * AROW + ks * 32 + kh);
#pragma unroll
      for (int jp = 0; jp < 4; jp++) {
        uint32_t b0, b1, b2, b3;
        ldsm4(b0, b1, b2, b3,
              kbuf + (jp * 16 + e8 + l7) * AROW + ks * 32 + kh);
#pragma unroll
        for (int i = 0; i < 2; i++) {
          mmaf16(sacc[i][2 * jp],     a[i][0], a[i][1], a[i][2], a[i][3], b0, b2);
          mmaf16(sacc[i][2 * jp + 1], a[i][0], a[i][1], a[i][2], a[i][3], b1, b3);
        }
      }
    }

    // ---- max-reduce + alpha (per row-slot) ----
    float al[4];
#pragma unroll
    for (int i = 0; i < 2; i++) {
#pragma unroll
      for (int rh = 0; rh < 2; rh++) {
        const int s = i * 2 + rh;
        float mx = -CUDART_INF_F;
#pragma unroll
        for (int j = 0; j < 8; j++)
          mx = fmaxf(mx, fmaxf(sacc[i][j][2 * rh], sacc[i][j][2 * rh + 1]));
        mx = fmaxf(mx, __shfl_xor_sync(0xffffffffu, mx, 1));
        mx = fmaxf(mx, __shfl_xor_sync(0xffffffffu, mx, 2));
        float mnew = fmaxf(mi[s], mx);
        al[s] = ex2(mi[s] - mnew);
        mi[s] = mnew;
      }
    }

    // ---- warp-uniform skip of o-rescale when every alpha is exactly 1 ----
    bool mine = (al[0] == 1.f) & (al[1] == 1.f) & (al[2] == 1.f) & (al[3] == 1.f);
    if (!__all_sync(0xffffffffu, mine)) {
#pragma unroll
      for (int i = 0; i < 2; i++)
#pragma unroll
        for (int rh = 0; rh < 2; rh++) {
          const int s = i * 2 + rh;
#pragma unroll
          for (int j = 0; j < 8; j++) {
            o[i][j][2 * rh]     *= al[s];
            o[i][j][2 * rh + 1] *= al[s];
          }
        }
    }

    // ---- p = 2^(s - m) in packed fp16 (PV A-fragment layout) ----
    uint32_t pah[2][4][4];
#pragma unroll
    for (int i = 0; i < 2; i++) {
      const float m0f = mi[i * 2], m1f = mi[i * 2 + 1];
#pragma unroll
      for (int ks2 = 0; ks2 < 4; ks2++) {
        pah[i][ks2][0] = ex2h2(pack2(sacc[i][2 * ks2][0] - m0f,
                                     sacc[i][2 * ks2][1] - m0f));
        pah[i][ks2][1] = ex2h2(pack2(sacc[i][2 * ks2][2] - m1f,
                                     sacc[i][2 * ks2][3] - m1f));
        pah[i][ks2][2] = ex2h2(pack2(sacc[i][2 * ks2 + 1][0] - m0f,
                                     sacc[i][2 * ks2 + 1][1] - m0f));
        pah[i][ks2][3] = ex2h2(pack2(sacc[i][2 * ks2 + 1][2] - m1f,
                                     sacc[i][2 * ks2 + 1][3] - m1f));
      }
    }

    // ---- O += P @ V ; rsum += P @ ones (row sums on tensor core) ----
    float rsum[2][4] = {};
#pragma unroll
    for (int ks2 = 0; ks2 < 4; ks2++) {
#pragma unroll
      for (int jp = 0; jp < 4; jp++) {
        uint32_t v0, v1, v2, v3;
        ldsm4t(v0, v1, v2, v3,
               vbuf + (ks2 * 16 + e8 + l7) * AROW + jp * 32 + kh);
#pragma unroll
        for (int i = 0; i < 2; i++) {
          mmaf16(o[i][2 * jp],     pah[i][ks2][0], pah[i][ks2][1],
                 pah[i][ks2][2], pah[i][ks2][3], v0, v1);
          mmaf16(o[i][2 * jp + 1], pah[i][ks2][0], pah[i][ks2][1],
                 pah[i][ks2][2], pah[i][ks2][3], v2, v3);
        }
      }
#pragma unroll
      for (int i = 0; i < 2; i++)
        mmaf16(rsum[i], pah[i][ks2][0], pah[i][ks2][1],
               pah[i][ks2][2], pah[i][ks2][3], ONE2, ONE2);
    }

    // ---- deferred li update ----
#pragma unroll
    for (int i = 0; i < 2; i++) {
#pragma unroll
      for (int rh = 0; rh < 2; rh++) {
        const int s = i * 2 + rh;
        li[s] = li[s] * al[s] + rsum[i][2 * rh];
      }
    }
  }

  // ---- epilogue (fp32 output, natural layout) ----
  const int n = nh / H_;
  const int h = nh - n * H_;
#pragma unroll
  for (int i = 0; i < 2; i++) {
#pragma unroll
    for (int rh = 0; rh < 2; rh++) {
      float inv = 1.f / li[i * 2 + rh];
      int t = qb * 128 + wbase + i * 16 + rh * 8 + g;
#pragma unroll
      for (int j = 0; j < 8; j++) {
        int d = j * 8 + 2 * t4;
        *reinterpret_cast<float2*>(
            &out[((size_t)n * T_ + t) * E_ + h * D_ + d]) =
            make_float2(o[i][j][2 * rh] * inv, o[i][j][2 * rh + 1] * inv);
      }
    }
  }
}

extern "C" void kernel_launch(void* const* d_in, const int* in_sizes, int n_in,
                              void* d_out, int out_size) {
  const float* x  = (const float*)d_in[0];
  const float* Wq = (const float*)d_in[1];
  const float* Wk = (const float*)d_in[2];
  const float* Wv = (const float*)d_in[3];
  float* out = (float*)d_out;

  round_kernel<<<(TOT4 + 255) / 256, 256>>>(x, Wq, Wk, Wv);

  const int qkv_smem = 4 * QBUF;   // 73728 B
  cudaFuncSetAttribute(qkv_kernel, cudaFuncAttributeMaxDynamicSharedMemorySize,
                       qkv_smem);
  dim3 gq(NT_ / 128, E_ / 128, 3);
  qkv_kernel<<<gq, 256, qkv_smem>>>();

  const int attn_smem = 128 * AROW + 4 * KVBUF;  // 55296 B
  cudaFuncSetAttribute(attn_kernel, cudaFuncAttributeMaxDynamicSharedMemorySize,
                       attn_smem);
  dim3 ga(T_ / 128, NH_);
  attn_kernel<<<ga, 128, attn_smem>>>(out);
}